// round 7
// baseline (speedup 1.0000x reference)
#include <cuda_runtime.h>
#include <cuda_bf16.h>
#include <math.h>
#include <stdint.h>

#define SQ 2048
#define DM 2048
#define NH 32
#define NKV 8
#define HD 64
#define WIN 1024
#define KVD (NKV*HD)

// ---------------- scratch (device globals) -----------------------------------
__device__ __nv_bfloat16 g_xh [SQ*DM],  g_xl [SQ*DM];
__device__ __nv_bfloat16 g_wqh[DM*DM],  g_wql[DM*DM];    // [N][K]
__device__ __nv_bfloat16 g_wkh[KVD*DM], g_wkl[KVD*DM];
__device__ __nv_bfloat16 g_wvh[KVD*DM], g_wvl[KVD*DM];
__device__ __nv_bfloat16 g_woh[DM*DM],  g_wol[DM*DM];
__device__ __nv_bfloat16 g_Qh [SQ*DM],  g_Ql [SQ*DM];    // rope'd, scaled
__device__ __nv_bfloat16 g_Kh [SQ*KVD], g_Kl [SQ*KVD];   // rope'd
__device__ __nv_bfloat16 g_Vh [SQ*KVD], g_Vl [SQ*KVD];
__device__ __nv_bfloat16 g_aoh[SQ*DM],  g_aol[SQ*DM];

// ---------------- helpers -----------------------------------------------------
__device__ __forceinline__ uint32_t smem_u32(const void* p) {
    uint32_t a;
    asm("{ .reg .u64 t; cvta.to.shared.u64 t, %1; cvt.u32.u64 %0, t; }" : "=r"(a) : "l"(p));
    return a;
}
__device__ __forceinline__ uint32_t sw128(uint32_t o) { return o ^ ((o >> 3) & 0x70); }

__device__ __forceinline__ void cp16(uint32_t s, const void* g) {
    asm volatile("cp.async.cg.shared.global [%0], [%1], 16;" :: "r"(s), "l"(g));
}
__device__ __forceinline__ void cp_commit() { asm volatile("cp.async.commit_group;" ::: "memory"); }
template<int N> __device__ __forceinline__ void cp_wait() {
    asm volatile("cp.async.wait_group %0;" :: "n"(N) : "memory");
}

__device__ __forceinline__ void ldsm_x4(uint32_t* r, uint32_t addr) {
    asm volatile("ldmatrix.sync.aligned.m8n8.x4.shared.b16 {%0,%1,%2,%3}, [%4];"
                 : "=r"(r[0]), "=r"(r[1]), "=r"(r[2]), "=r"(r[3]) : "r"(addr));
}
__device__ __forceinline__ void ldsm_x4t(uint32_t* r, uint32_t addr) {
    asm volatile("ldmatrix.sync.aligned.m8n8.x4.trans.shared.b16 {%0,%1,%2,%3}, [%4];"
                 : "=r"(r[0]), "=r"(r[1]), "=r"(r[2]), "=r"(r[3]) : "r"(addr));
}
__device__ __forceinline__ void mma16816(float* c, const uint32_t* a, const uint32_t* b) {
    asm volatile("mma.sync.aligned.m16n8k16.row.col.f32.bf16.bf16.f32 "
                 "{%0,%1,%2,%3}, {%4,%5,%6,%7}, {%8,%9}, {%0,%1,%2,%3};"
                 : "+f"(c[0]), "+f"(c[1]), "+f"(c[2]), "+f"(c[3])
                 : "r"(a[0]), "r"(a[1]), "r"(a[2]), "r"(a[3]), "r"(b[0]), "r"(b[1]));
}
__device__ __forceinline__ uint32_t pack_bf16(float lo, float hi) {
    uint32_t r;
    asm("cvt.rn.bf16x2.f32 %0, %1, %2;" : "=r"(r) : "f"(hi), "f"(lo));
    return r;
}
__device__ __forceinline__ void split2(float v0, float v1, uint32_t& hp, uint32_t& lp) {
    hp = pack_bf16(v0, v1);
    float f0 = __uint_as_float(hp << 16);
    float f1 = __uint_as_float(hp & 0xffff0000u);
    lp = pack_bf16(v0 - f0, v1 - f1);
}

// ---------------- pre-pass: split x ------------------------------------------
__global__ void split_kernel(const float* __restrict__ X, __nv_bfloat16* __restrict__ H,
                             __nv_bfloat16* __restrict__ L, int n4)
{
    int i = blockIdx.x * blockDim.x + threadIdx.x;
    if (i >= n4) return;
    float4 v = ((const float4*)X)[i];
    uint32_t h0, l0, h1, l1;
    split2(v.x, v.y, h0, l0);
    split2(v.z, v.w, h1, l1);
    ((uint32_t*)H)[2*i] = h0; ((uint32_t*)H)[2*i+1] = h1;
    ((uint32_t*)L)[2*i] = l0; ((uint32_t*)L)[2*i+1] = l1;
}

// ---------------- pre-pass: all-weight transpose+split, one launch -------------
__device__ __forceinline__ void tsplit_tile(const float* __restrict__ W,
                                            __nv_bfloat16* __restrict__ Th,
                                            __nv_bfloat16* __restrict__ Tl,
                                            int K, int N, int tile, float (*t)[33])
{
    const int tid = threadIdx.x;
    const int ntn = N >> 5;
    const int k0 = (tile / ntn) << 6;
    const int n0 = (tile % ntn) << 5;
#pragma unroll
    for (int it = 0; it < 8; it++) {
        int idx = tid + it * 256;
        int r = idx >> 5, c = idx & 31;
        t[r][c] = W[(size_t)(k0 + r) * N + n0 + c];
    }
    __syncthreads();
    const int n  = tid >> 3;
    const int kk = tid & 7;
#pragma unroll
    for (int it = 0; it < 4; it++) {
        int kp = kk + it * 8;
        uint32_t hp, lp;
        split2(t[2*kp][n], t[2*kp+1][n], hp, lp);
        size_t o = (size_t)(n0 + n) * K + k0 + 2 * kp;
        *(uint32_t*)(Th + o) = hp;
        *(uint32_t*)(Tl + o) = lp;
    }
    __syncthreads();
}

__global__ __launch_bounds__(256)
void transpose_split_all(const float* __restrict__ wq, const float* __restrict__ wk,
                         const float* __restrict__ wv, const float* __restrict__ wo,
                         __nv_bfloat16* wqh, __nv_bfloat16* wql,
                         __nv_bfloat16* wkh, __nv_bfloat16* wkl,
                         __nv_bfloat16* wvh, __nv_bfloat16* wvl,
                         __nv_bfloat16* woh, __nv_bfloat16* wol)
{
    __shared__ float t[64][33];
    int b = blockIdx.x;
    if (b < 2048)        tsplit_tile(wq, wqh, wql, DM, DM,  b,        t);
    else if (b < 2560)   tsplit_tile(wk, wkh, wkl, DM, KVD, b - 2048, t);
    else if (b < 3072)   tsplit_tile(wv, wvh, wvl, DM, KVD, b - 2560, t);
    else                 tsplit_tile(wo, woh, wol, DM, DM,  b - 3072, t);
}

// ---------------- GEMM core: 3-stage cp.async, 128x128 tile, BK=64 -------------
// Register budget: acc 64 + B frags 32 + A frags 8 + addressing < 128 (no spills).
static constexpr int GEMM_SMEM = 3 * 65536;

struct GemmAcc { float a[4][4][4]; };

__device__ __forceinline__ void gemm_mainloop(
    const __nv_bfloat16* __restrict__ Ah, const __nv_bfloat16* __restrict__ Al,
    const __nv_bfloat16* __restrict__ Bh, const __nv_bfloat16* __restrict__ Bl,
    int brow, int bcol, int K, uint32_t sbase, GemmAcc& acc)
{
    const int tid  = threadIdx.x;
    const int warp = tid >> 5;
    const int lane = tid & 31;
    const int wm   = (warp & 1) * 64;
    const int wn   = (warp >> 1) * 32;

    const int a_r   = (lane & 7) + 8 * ((lane >> 3) & 1);
    const int a_kb  = 16 * (lane >> 4);
    const int bx_r  = lane & 7;
    const int bx_nt = lane >> 4;
    const int bx_kb = 16 * ((lane >> 3) & 1);

    auto load_stage = [&](int s, int k0) {
        uint32_t base = sbase + s * 65536;
#pragma unroll
        for (int it = 0; it < 4; it++) {
            int idx = tid + it * 256;
            int r   = idx >> 3;
            int c   = idx & 7;
            uint32_t off = sw128((uint32_t)(r * 128 + c * 16));
            cp16(base + off,         Ah + (size_t)(brow + r) * K + k0 + c * 8);
            cp16(base + 16384 + off, Al + (size_t)(brow + r) * K + k0 + c * 8);
            cp16(base + 32768 + off, Bh + (size_t)(bcol + r) * K + k0 + c * 8);
            cp16(base + 49152 + off, Bl + (size_t)(bcol + r) * K + k0 + c * 8);
        }
    };

    const int nch = K >> 6;
    load_stage(0, 0);  cp_commit();
    load_stage(1, 64); cp_commit();

    int s = 0;
    for (int c = 0; c < nch; c++) {
        if (c + 2 < nch) load_stage((s + 2 >= 3) ? s - 1 : s + 2, (c + 2) << 6);
        cp_commit();
        cp_wait<2>();
        __syncthreads();

        uint32_t base = sbase + s * 65536;
#pragma unroll
        for (int ks = 0; ks < 4; ks++) {
            const int kb = ks * 32;
            uint32_t bh[4][2], bl[4][2];
#pragma unroll
            for (int ntp = 0; ntp < 2; ntp++) {
                uint32_t off = sw128((uint32_t)((wn + (2*ntp + bx_nt) * 8 + bx_r) * 128 + kb + bx_kb));
                uint32_t r[4];
                ldsm_x4(r, base + 32768 + off);
                bh[2*ntp][0] = r[0]; bh[2*ntp][1] = r[1];
                bh[2*ntp+1][0] = r[2]; bh[2*ntp+1][1] = r[3];
                ldsm_x4(r, base + 49152 + off);
                bl[2*ntp][0] = r[0]; bl[2*ntp][1] = r[1];
                bl[2*ntp+1][0] = r[2]; bl[2*ntp+1][1] = r[3];
            }
#pragma unroll
            for (int mt = 0; mt < 4; mt++) {
                uint32_t ah[4], al[4];
                uint32_t aoff = sw128((uint32_t)((wm + mt * 16 + a_r) * 128 + kb + a_kb));
                ldsm_x4(ah, base + aoff);
                ldsm_x4(al, base + 16384 + aoff);
#pragma unroll
                for (int nt = 0; nt < 4; nt++) mma16816(acc.a[mt][nt], ah, bh[nt]);
#pragma unroll
                for (int nt = 0; nt < 4; nt++) mma16816(acc.a[mt][nt], al, bh[nt]);
#pragma unroll
                for (int nt = 0; nt < 4; nt++) mma16816(acc.a[mt][nt], ah, bl[nt]);
            }
        }
        __syncthreads();
        s = (s + 1 >= 3) ? 0 : s + 1;
    }
}

// Fused QKV projection: grid.x = 24 (0-15 Q | 16-19 K | 20-23 V), grid.y = 16.
__global__ __launch_bounds__(256, 2)
void qkv_gemm(const __nv_bfloat16* __restrict__ xh, const __nv_bfloat16* __restrict__ xl,
              const __nv_bfloat16* __restrict__ wqh, const __nv_bfloat16* __restrict__ wql,
              const __nv_bfloat16* __restrict__ wkh, const __nv_bfloat16* __restrict__ wkl,
              const __nv_bfloat16* __restrict__ wvh, const __nv_bfloat16* __restrict__ wvl,
              __nv_bfloat16* __restrict__ qh, __nv_bfloat16* __restrict__ ql,
              __nv_bfloat16* __restrict__ kh, __nv_bfloat16* __restrict__ kl,
              __nv_bfloat16* __restrict__ vh, __nv_bfloat16* __restrict__ vl,
              const float* __restrict__ fc, const float* __restrict__ fs)
{
    extern __shared__ char sm[];
    const uint32_t sbase = smem_u32(sm);
    const int bx   = blockIdx.x;
    const int brow = blockIdx.y * 128;

    const __nv_bfloat16 *Bh, *Bl;
    __nv_bfloat16 *Ch, *Cl;
    int N, bcol, mode;
    if (bx < 16)      { Bh = wqh; Bl = wql; Ch = qh; Cl = ql; N = DM;  bcol = bx * 128;        mode = 1; }
    else if (bx < 20) { Bh = wkh; Bl = wkl; Ch = kh; Cl = kl; N = KVD; bcol = (bx - 16) * 128; mode = 2; }
    else              { Bh = wvh; Bl = wvl; Ch = vh; Cl = vl; N = KVD; bcol = (bx - 20) * 128; mode = 3; }

    GemmAcc acc;
#pragma unroll
    for (int i = 0; i < 4; i++)
#pragma unroll
        for (int j = 0; j < 4; j++)
#pragma unroll
            for (int e = 0; e < 4; e++) acc.a[i][j][e] = 0.f;

    gemm_mainloop(xh, xl, Bh, Bl, brow, bcol, DM, sbase, acc);

    const int warp = threadIdx.x >> 5;
    const int lane = threadIdx.x & 31;
    const int mrow0 = brow + (warp & 1) * 64 + (lane >> 2);
    const int ncol0 = bcol + (warp >> 1) * 32 + 2 * (lane & 3);
#pragma unroll
    for (int mt = 0; mt < 4; mt++) {
#pragma unroll
        for (int half = 0; half < 2; half++) {
            const int m = mrow0 + mt * 16 + half * 8;
#pragma unroll
            for (int nt = 0; nt < 4; nt++) {
                float v0 = acc.a[mt][nt][half * 2];
                float v1 = acc.a[mt][nt][half * 2 + 1];
                const int n = ncol0 + nt * 8;
                if (mode != 3) {
                    int p = (n & (HD - 1)) >> 1;
                    float cs = fc[m * (HD / 2) + p];
                    float sn = fs[m * (HD / 2) + p];
                    float a = v0, b = v1;
                    v0 = a * cs - b * sn;
                    v1 = a * sn + b * cs;
                    if (mode == 1) { v0 *= 0.125f; v1 *= 0.125f; }
                }
                uint32_t hp, lp;
                split2(v0, v1, hp, lp);
                *(uint32_t*)(Ch + (size_t)m * N + n) = hp;
                *(uint32_t*)(Cl + (size_t)m * N + n) = lp;
            }
        }
    }
}

__global__ __launch_bounds__(256, 2)
void out_gemm(const __nv_bfloat16* __restrict__ Ah, const __nv_bfloat16* __restrict__ Al,
              const __nv_bfloat16* __restrict__ Bh, const __nv_bfloat16* __restrict__ Bl,
              float* __restrict__ C)
{
    extern __shared__ char sm[];
    const uint32_t sbase = smem_u32(sm);
    const int brow = blockIdx.y * 128;
    const int bcol = blockIdx.x * 128;

    GemmAcc acc;
#pragma unroll
    for (int i = 0; i < 4; i++)
#pragma unroll
        for (int j = 0; j < 4; j++)
#pragma unroll
            for (int e = 0; e < 4; e++) acc.a[i][j][e] = 0.f;

    gemm_mainloop(Ah, Al, Bh, Bl, brow, bcol, DM, sbase, acc);

    const int warp = threadIdx.x >> 5;
    const int lane = threadIdx.x & 31;
    const int mrow0 = brow + (warp & 1) * 64 + (lane >> 2);
    const int ncol0 = bcol + (warp >> 1) * 32 + 2 * (lane & 3);
#pragma unroll
    for (int mt = 0; mt < 4; mt++) {
#pragma unroll
        for (int half = 0; half < 2; half++) {
            const int m = mrow0 + mt * 16 + half * 8;
#pragma unroll
            for (int nt = 0; nt < 4; nt++) {
                const int n = ncol0 + nt * 8;
                *(float2*)(C + (size_t)m * DM + n) =
                    make_float2(acc.a[mt][nt][half * 2], acc.a[mt][nt][half * 2 + 1]);
            }
        }
    }
}

// ---------------- MMA flash attention: 128 queries/CTA, 8 warps ----------------
// Register budget: O 32 + qfh 16 + per-phase frags <= 40 + state < 128 (no spills).
static constexpr int ATTN_SMEM = 32768 + 2 * 32768;

__global__ __launch_bounds__(256, 2)
void attn_mma(const __nv_bfloat16* __restrict__ Qh, const __nv_bfloat16* __restrict__ Ql,
              const __nv_bfloat16* __restrict__ Kh, const __nv_bfloat16* __restrict__ Kl,
              const __nv_bfloat16* __restrict__ Vh, const __nv_bfloat16* __restrict__ Vl,
              __nv_bfloat16* __restrict__ Oh, __nv_bfloat16* __restrict__ Ol)
{
    extern __shared__ char sm[];
    const uint32_t sb = smem_u32(sm);
    const int tid  = threadIdx.x;
    const int warp = tid >> 5;
    const int lane = tid & 31;
    const int qt   = blockIdx.x;
    const int h    = blockIdx.y;
    const int kvh  = h >> 2;
    const int qb   = qt * 128;

    const uint32_t sQh = sb, sQl = sb + 16384;
    const uint32_t st0 = sb + 32768;

    const int kt0   = max(0, (qb - WIN) >> 6);
    const int ktmax = 2 * qt + 1;

#pragma unroll
    for (int it = 0; it < 4; it++) {
        int idx = tid + it * 256;
        int r = idx >> 3, c = idx & 7;
        uint32_t off = sw128((uint32_t)(r * 128 + c * 16));
        size_t go = (size_t)(qb + r) * DM + h * HD + c * 8;
        cp16(sQh + off, Qh + go);
        cp16(sQl + off, Ql + go);
    }
    auto load_kv = [&](uint32_t base, int kt) {
#pragma unroll
        for (int it = 0; it < 2; it++) {
            int idx = tid + it * 256;
            int r = idx >> 3, c = idx & 7;
            uint32_t off = sw128((uint32_t)(r * 128 + c * 16));
            size_t go = (size_t)(kt * 64 + r) * KVD + kvh * HD + c * 8;
            cp16(base + off,         Kh + go);
            cp16(base + 8192 + off,  Kl + go);
            cp16(base + 16384 + off, Vh + go);
            cp16(base + 24576 + off, Vl + go);
        }
    };
    load_kv(st0, kt0);
    cp_commit();
    cp_wait<0>();
    __syncthreads();

    // Q hi fragments persistent; Q lo reloaded per tile (register pressure).
    const int a_r  = warp * 16 + (lane & 7) + 8 * ((lane >> 3) & 1);
    const int a_kb = 16 * (lane >> 4);
    uint32_t qfh[4][4];
#pragma unroll
    for (int ks = 0; ks < 4; ks++)
        ldsm_x4(qfh[ks], sQh + sw128((uint32_t)(a_r * 128 + ks * 32 + a_kb)));

    float O[8][4];
#pragma unroll
    for (int nt = 0; nt < 8; nt++)
#pragma unroll
        for (int e = 0; e < 4; e++) O[nt][e] = 0.f;
    float m0 = -1e20f, m1 = -1e20f, l0 = 0.f, l1 = 0.f;

    const int i0 = qb + warp * 16 + (lane >> 2);
    const int i1 = i0 + 8;
    const int jc = 2 * (lane & 3);
    const int wrow0 = qb + warp * 16;
    const int kx_r  = lane & 7;
    const int kx_nt = lane >> 4;
    const int kx_kb = 16 * ((lane >> 3) & 1);
    const int vx_r  = lane & 15;
    const int vx_nt = lane >> 4;

    for (int kt = kt0; kt <= ktmax; kt++) {
        const int buf = (kt - kt0) & 1;
        if (kt < ktmax) { load_kv(st0 + (buf ^ 1) * 32768, kt + 1); cp_commit(); cp_wait<1>(); }
        else            { cp_wait<0>(); }
        __syncthreads();

        const int ktb = kt * 64;
        const bool act = (ktb <= wrow0 + 15) && (ktb + 63 >= wrow0 - WIN);
        if (act) {
            const uint32_t bK_h = st0 + buf * 32768;
            const uint32_t bK_l = bK_h + 8192;
            const uint32_t bV_h = bK_h + 16384;
            const uint32_t bV_l = bK_h + 24576;

            float S[8][4];
#pragma unroll
            for (int nt = 0; nt < 8; nt++)
#pragma unroll
                for (int e = 0; e < 4; e++) S[nt][e] = 0.f;

            // ---- S = Q @ K^T, 3-term, low register footprint
#pragma unroll
            for (int ks = 0; ks < 4; ks++) {
                const int kb = ks * 32;
                uint32_t qlk[4];
                ldsm_x4(qlk, sQl + sw128((uint32_t)(a_r * 128 + kb + a_kb)));
#pragma unroll
                for (int grp = 0; grp < 2; grp++) {
                    uint32_t kf[4][2];
#pragma unroll
                    for (int p = 0; p < 2; p++) {
                        int ntp = grp * 2 + p;
                        uint32_t off = sw128((uint32_t)(((2*ntp + kx_nt) * 8 + kx_r) * 128 + kb + kx_kb));
                        uint32_t r[4];
                        ldsm_x4(r, bK_h + off);
                        kf[2*p][0] = r[0]; kf[2*p][1] = r[1];
                        kf[2*p+1][0] = r[2]; kf[2*p+1][1] = r[3];
                    }
#pragma unroll
                    for (int n = 0; n < 4; n++) mma16816(S[grp*4+n], qfh[ks], kf[n]);
#pragma unroll
                    for (int n = 0; n < 4; n++) mma16816(S[grp*4+n], qlk, kf[n]);
#pragma unroll
                    for (int p = 0; p < 2; p++) {
                        int ntp = grp * 2 + p;
                        uint32_t off = sw128((uint32_t)(((2*ntp + kx_nt) * 8 + kx_r) * 128 + kb + kx_kb));
                        uint32_t r[4];
                        ldsm_x4(r, bK_l + off);
                        kf[2*p][0] = r[0]; kf[2*p][1] = r[1];
                        kf[2*p+1][0] = r[2]; kf[2*p+1][1] = r[3];
                    }
#pragma unroll
                    for (int n = 0; n < 4; n++) mma16816(S[grp*4+n], qfh[ks], kf[n]);
                }
            }

            const bool full = (ktb >= qb + 127 - WIN) && (ktb + 64 <= qb);
            if (!full) {
#pragma unroll
                for (int nt = 0; nt < 8; nt++) {
                    int j = ktb + nt * 8 + jc;
                    if (j > i0 || j < i0 - WIN)         S[nt][0] = -1e30f;
                    if (j + 1 > i0 || j + 1 < i0 - WIN) S[nt][1] = -1e30f;
                    if (j > i1 || j < i1 - WIN)         S[nt][2] = -1e30f;
                    if (j + 1 > i1 || j + 1 < i1 - WIN) S[nt][3] = -1e30f;
                }
            }

            float mx0 = -1e30f, mx1 = -1e30f;
#pragma unroll
            for (int nt = 0; nt < 8; nt++) {
                mx0 = fmaxf(mx0, fmaxf(S[nt][0], S[nt][1]));
                mx1 = fmaxf(mx1, fmaxf(S[nt][2], S[nt][3]));
            }
            mx0 = fmaxf(mx0, __shfl_xor_sync(0xffffffffu, mx0, 1));
            mx0 = fmaxf(mx0, __shfl_xor_sync(0xffffffffu, mx0, 2));
            mx1 = fmaxf(mx1, __shfl_xor_sync(0xffffffffu, mx1, 1));
            mx1 = fmaxf(mx1, __shfl_xor_sync(0xffffffffu, mx1, 2));
            const float mn0 = fmaxf(m0, mx0);
            const float mn1 = fmaxf(m1, mx1);
            const bool stable = __all_sync(0xffffffffu, (mn0 == m0) & (mn1 == m1));
            if (!stable) {
                const float sc0 = exp2f((m0 - mn0) * 1.44269504f);
                const float sc1 = exp2f((m1 - mn1) * 1.44269504f);
                m0 = mn0; m1 = mn1;
                l0 *= sc0; l1 *= sc1;
#pragma unroll
                for (int nt = 0; nt < 8; nt++) {
                    O[nt][0] *= sc0; O[nt][1] *= sc0;
                    O[nt][2] *= sc1; O[nt][3] *= sc1;
                }
            }
            float rs0 = 0.f, rs1 = 0.f;
#pragma unroll
            for (int nt = 0; nt < 8; nt++) {
                S[nt][0] = exp2f((S[nt][0] - m0) * 1.44269504f);
                S[nt][1] = exp2f((S[nt][1] - m0) * 1.44269504f);
                S[nt][2] = exp2f((S[nt][2] - m1) * 1.44269504f);
                S[nt][3] = exp2f((S[nt][3] - m1) * 1.44269504f);
                rs0 += S[nt][0] + S[nt][1];
                rs1 += S[nt][2] + S[nt][3];
            }
            rs0 += __shfl_xor_sync(0xffffffffu, rs0, 1);
            rs0 += __shfl_xor_sync(0xffffffffu, rs0, 2);
            rs1 += __shfl_xor_sync(0xffffffffu, rs1, 1);
            rs1 += __shfl_xor_sync(0xffffffffu, rs1, 2);
            l0 += rs0; l1 += rs1;

            // pack P (reuses S's registers as they die)
            uint32_t pah[4][4], pal[4][4];
#pragma unroll
            for (int ks = 0; ks < 4; ks++) {
                split2(S[2*ks][0],   S[2*ks][1],   pah[ks][0], pal[ks][0]);
                split2(S[2*ks][2],   S[2*ks][3],   pah[ks][1], pal[ks][1]);
                split2(S[2*ks+1][0], S[2*ks+1][1], pah[ks][2], pal[ks][2]);
                split2(S[2*ks+1][2], S[2*ks+1][3], pah[ks][3], pal[ks][3]);
            }

            // ---- O += P @ V, 3-term, nt groups of 4
#pragma unroll
            for (int ks = 0; ks < 4; ks++) {
#pragma unroll
                for (int grp = 0; grp < 2; grp++) {
                    uint32_t vf[4][2];
#pragma unroll
                    for (int p = 0; p < 2; p++) {
                        int ntp = grp * 2 + p;
                        uint32_t off = sw128((uint32_t)((ks * 16 + vx_r) * 128 + (2*ntp + vx_nt) * 16));
                        uint32_t r[4];
                        ldsm_x4t(r, bV_h + off);
                        vf[2*p][0] = r[0]; vf[2*p][1] = r[1];
                        vf[2*p+1][0] = r[2]; vf[2*p+1][1] = r[3];
                    }
#pragma unroll
                    for (int n = 0; n < 4; n++) mma16816(O[grp*4+n], pah[ks], vf[n]);
#pragma unroll
                    for (int n = 0; n < 4; n++) mma16816(O[grp*4+n], pal[ks], vf[n]);
#pragma unroll
                    for (int p = 0; p < 2; p++) {
                        int ntp = grp * 2 + p;
                        uint32_t off = sw128((uint32_t)((ks * 16 + vx_r) * 128 + (2*ntp + vx_nt) * 16));
                        uint32_t r[4];
                        ldsm_x4t(r, bV_l + off);
                        vf[2*p][0] = r[0]; vf[2*p][1] = r[1];
                        vf[2*p+1][0] = r[2]; vf[2*p+1][1] = r[3];
                    }
#pragma unroll
                    for (int n = 0; n < 4; n++) mma16816(O[grp*4+n], pah[ks], vf[n]);
                }
            }
        }
        __syncthreads();
    }

    const float inv0 = 1.f / l0;
    const float inv1 = 1.f / l1;
    const int row0 = qb + warp * 16 + (lane >> 2);
    const int colb = h * HD + jc;
#pragma unroll
    for (int nt = 0; nt < 8; nt++) {
        uint32_t hp, lp;
        split2(O[nt][0] * inv0, O[nt][1] * inv0, hp, lp);
        size_t o = (size_t)row0 * DM + colb + nt * 8;
        *(uint32_t*)(Oh + o) = hp;
        *(uint32_t*)(Ol + o) = lp;
        split2(O[nt][2] * inv1, O[nt][3] * inv1, hp, lp);
        o += (size_t)8 * DM;
        *(uint32_t*)(Oh + o) = hp;
        *(uint32_t*)(Ol + o) = lp;
    }
}

// ---------------- launch --------------------------------------------------------
extern "C" void kernel_launch(void* const* d_in, const int* in_sizes, int n_in,
                              void* d_out, int out_size)
{
    const float* x  = (const float*)d_in[0];
    const float* wq = (const float*)d_in[1];
    const float* wk = (const float*)d_in[2];
    const float* wv = (const float*)d_in[3];
    const float* wo = (const float*)d_in[4];
    const float* fc = (const float*)d_in[5];
    const float* fs = (const float*)d_in[6];
    float* out = (float*)d_out;

    __nv_bfloat16 *xh, *xl, *wqh, *wql, *wkh, *wkl, *wvh, *wvl, *woh, *wol;
    __nv_bfloat16 *qh, *ql, *kh, *kl, *vh, *vl, *aoh, *aol;
    cudaGetSymbolAddress((void**)&xh,  g_xh);  cudaGetSymbolAddress((void**)&xl,  g_xl);
    cudaGetSymbolAddress((void**)&wqh, g_wqh); cudaGetSymbolAddress((void**)&wql, g_wql);
    cudaGetSymbolAddress((void**)&wkh, g_wkh); cudaGetSymbolAddress((void**)&wkl, g_wkl);
    cudaGetSymbolAddress((void**)&wvh, g_wvh); cudaGetSymbolAddress((void**)&wvl, g_wvl);
    cudaGetSymbolAddress((void**)&woh, g_woh); cudaGetSymbolAddress((void**)&wol, g_wol);
    cudaGetSymbolAddress((void**)&qh,  g_Qh);  cudaGetSymbolAddress((void**)&ql,  g_Ql);
    cudaGetSymbolAddress((void**)&kh,  g_Kh);  cudaGetSymbolAddress((void**)&kl,  g_Kl);
    cudaGetSymbolAddress((void**)&vh,  g_Vh);  cudaGetSymbolAddress((void**)&vl,  g_Vl);
    cudaGetSymbolAddress((void**)&aoh, g_aoh); cudaGetSymbolAddress((void**)&aol, g_aol);

    cudaFuncSetAttribute(qkv_gemm, cudaFuncAttributeMaxDynamicSharedMemorySize, GEMM_SMEM);
    cudaFuncSetAttribute(out_gemm, cudaFuncAttributeMaxDynamicSharedMemorySize, GEMM_SMEM);
    cudaFuncSetAttribute(attn_mma, cudaFuncAttributeMaxDynamicSharedMemorySize, ATTN_SMEM);

    const int n4 = SQ * DM / 4;
    split_kernel<<<n4 / 256, 256>>>(x, xh, xl, n4);
    transpose_split_all<<<5120, 256>>>(wq, wk, wv, wo,
                                       wqh, wql, wkh, wkl, wvh, wvl, woh, wol);

    qkv_gemm<<<dim3(24, 16), 256, GEMM_SMEM>>>(xh, xl, wqh, wql, wkh, wkl, wvh, wvl,
                                               qh, ql, kh, kl, vh, vl, fc, fs);

    attn_mma<<<dim3(SQ / 128, NH), 256, ATTN_SMEM>>>(qh, ql, kh, kl, vh, vl, aoh, aol);

    out_gemm<<<dim3(16, 16), 256, GEMM_SMEM>>>(aoh, aol, woh, wol, out);
}

// round 9
// speedup vs baseline: 1.4254x; 1.4254x over previous
#include <cuda_runtime.h>
#include <cuda_fp16.h>
#include <math.h>
#include <stdint.h>

#define SQ 2048
#define DM 2048
#define NH 32
#define NKV 8
#define HD 64
#define WIN 1024
#define KVD (NKV*HD)

// ---------------- scratch (device globals) -----------------------------------
__device__ __half g_xh [SQ*DM],  g_xl [SQ*DM];
__device__ __half g_wq [DM*DM];                 // [N][K] single fp16
__device__ __half g_wk [KVD*DM];
__device__ __half g_wv [KVD*DM];
__device__ __half g_woh[DM*DM],  g_wol[DM*DM];  // wo 2-term
__device__ __half g_Q  [SQ*DM];                 // rope'd, scaled, single fp16
__device__ __half g_K  [SQ*KVD];                // rope'd
__device__ __half g_V  [SQ*KVD];
__device__ __half g_aoh[SQ*DM], g_aol[SQ*DM];   // attention out, 2-term

// ---------------- helpers -----------------------------------------------------
__device__ __forceinline__ uint32_t smem_u32(const void* p) {
    uint32_t a;
    asm("{ .reg .u64 t; cvta.to.shared.u64 t, %1; cvt.u32.u64 %0, t; }" : "=r"(a) : "l"(p));
    return a;
}
__device__ __forceinline__ uint32_t sw128(uint32_t o) { return o ^ ((o >> 3) & 0x70); }

__device__ __forceinline__ void cp16(uint32_t s, const void* g) {
    asm volatile("cp.async.cg.shared.global [%0], [%1], 16;" :: "r"(s), "l"(g));
}
__device__ __forceinline__ void cp_commit() { asm volatile("cp.async.commit_group;" ::: "memory"); }
template<int N> __device__ __forceinline__ void cp_wait() {
    asm volatile("cp.async.wait_group %0;" :: "n"(N) : "memory");
}

__device__ __forceinline__ void ldsm_x4(uint32_t* r, uint32_t addr) {
    asm volatile("ldmatrix.sync.aligned.m8n8.x4.shared.b16 {%0,%1,%2,%3}, [%4];"
                 : "=r"(r[0]), "=r"(r[1]), "=r"(r[2]), "=r"(r[3]) : "r"(addr));
}
__device__ __forceinline__ void ldsm_x4t(uint32_t* r, uint32_t addr) {
    asm volatile("ldmatrix.sync.aligned.m8n8.x4.trans.shared.b16 {%0,%1,%2,%3}, [%4];"
                 : "=r"(r[0]), "=r"(r[1]), "=r"(r[2]), "=r"(r[3]) : "r"(addr));
}
// fp16 inputs, fp32 accumulate
__device__ __forceinline__ void mma16816(float* c, const uint32_t* a, const uint32_t* b) {
    asm volatile("mma.sync.aligned.m16n8k16.row.col.f32.f16.f16.f32 "
                 "{%0,%1,%2,%3}, {%4,%5,%6,%7}, {%8,%9}, {%0,%1,%2,%3};"
                 : "+f"(c[0]), "+f"(c[1]), "+f"(c[2]), "+f"(c[3])
                 : "r"(a[0]), "r"(a[1]), "r"(a[2]), "r"(a[3]), "r"(b[0]), "r"(b[1]));
}
__device__ __forceinline__ uint32_t pack_f16(float lo, float hi) {
    uint32_t r;
    asm("cvt.rn.f16x2.f32 %0, %1, %2;" : "=r"(r) : "f"(hi), "f"(lo));
    return r;
}
__device__ __forceinline__ void split2h(float v0, float v1, uint32_t& hp, uint32_t& lp) {
    hp = pack_f16(v0, v1);
    __half2 h = *reinterpret_cast<__half2*>(&hp);
    float f0 = __half2float(__low2half(h));
    float f1 = __half2float(__high2half(h));
    lp = pack_f16(v0 - f0, v1 - f1);
}

// ---------------- pre-pass: split x into fp16 hi/lo ----------------------------
__global__ void split_kernel(const float* __restrict__ X, __half* __restrict__ H,
                             __half* __restrict__ L, int n4)
{
    int i = blockIdx.x * blockDim.x + threadIdx.x;
    if (i >= n4) return;
    float4 v = ((const float4*)X)[i];
    uint32_t h0, l0, h1, l1;
    split2h(v.x, v.y, h0, l0);
    split2h(v.z, v.w, h1, l1);
    ((uint32_t*)H)[2*i] = h0; ((uint32_t*)H)[2*i+1] = h1;
    ((uint32_t*)L)[2*i] = l0; ((uint32_t*)L)[2*i+1] = l1;
}

// ---------------- pre-pass: weight transposes ----------------------------------
// single fp16 variant
__device__ __forceinline__ void t_tile1(const float* __restrict__ W, __half* __restrict__ T,
                                        int K, int N, int tile, float (*t)[33])
{
    const int tid = threadIdx.x;
    const int ntn = N >> 5;
    const int k0 = (tile / ntn) << 6;
    const int n0 = (tile % ntn) << 5;
#pragma unroll
    for (int it = 0; it < 8; it++) {
        int idx = tid + it * 256;
        int r = idx >> 5, c = idx & 31;
        t[r][c] = W[(size_t)(k0 + r) * N + n0 + c];
    }
    __syncthreads();
    const int n  = tid >> 3;
    const int kk = tid & 7;
#pragma unroll
    for (int it = 0; it < 4; it++) {
        int kp = kk + it * 8;
        *(uint32_t*)(T + (size_t)(n0 + n) * K + k0 + 2 * kp) =
            pack_f16(t[2*kp][n], t[2*kp+1][n]);
    }
    __syncthreads();
}
// hi/lo 2-term variant
__device__ __forceinline__ void t_tile2(const float* __restrict__ W,
                                        __half* __restrict__ Th, __half* __restrict__ Tl,
                                        int K, int N, int tile, float (*t)[33])
{
    const int tid = threadIdx.x;
    const int ntn = N >> 5;
    const int k0 = (tile / ntn) << 6;
    const int n0 = (tile % ntn) << 5;
#pragma unroll
    for (int it = 0; it < 8; it++) {
        int idx = tid + it * 256;
        int r = idx >> 5, c = idx & 31;
        t[r][c] = W[(size_t)(k0 + r) * N + n0 + c];
    }
    __syncthreads();
    const int n  = tid >> 3;
    const int kk = tid & 7;
#pragma unroll
    for (int it = 0; it < 4; it++) {
        int kp = kk + it * 8;
        uint32_t hp, lp;
        split2h(t[2*kp][n], t[2*kp+1][n], hp, lp);
        size_t o = (size_t)(n0 + n) * K + k0 + 2 * kp;
        *(uint32_t*)(Th + o) = hp;
        *(uint32_t*)(Tl + o) = lp;
    }
    __syncthreads();
}

__global__ __launch_bounds__(256)
void transpose_all(const float* __restrict__ wq, const float* __restrict__ wk,
                   const float* __restrict__ wv, const float* __restrict__ wo,
                   __half* twq, __half* twk, __half* twv,
                   __half* twoh, __half* twol)
{
    __shared__ float t[64][33];
    int b = blockIdx.x;
    if (b < 2048)        t_tile1(wq, twq, DM, DM,  b,        t);
    else if (b < 2560)   t_tile1(wk, twk, DM, KVD, b - 2048, t);
    else if (b < 3072)   t_tile1(wv, twv, DM, KVD, b - 2560, t);
    else                 t_tile2(wo, twoh, twol, DM, DM, b - 3072, t);
}

// ---------------- QKV GEMM: fp16 2-term, 2-stage, 128x128, BK=64 ----------------
// smem/stage: A_h 16K + A_l 16K + B 16K = 48K; 2 stages = 96K.
static constexpr int QKV_STAGE = 49152;
static constexpr int QKV_SMEM  = 2 * QKV_STAGE;

struct GemmAcc { float a[4][4][4]; };

__device__ __forceinline__ void qkv_mainloop(
    const __half* __restrict__ Ah, const __half* __restrict__ Al,
    const __half* __restrict__ B,
    int brow, int bcol, int K, uint32_t sbase, GemmAcc& acc)
{
    const int tid  = threadIdx.x;
    const int warp = tid >> 5;
    const int lane = tid & 31;
    const int wm   = (warp & 1) * 64;
    const int wn   = (warp >> 1) * 32;

    const int a_r   = (lane & 7) + 8 * ((lane >> 3) & 1);
    const int a_kb  = 16 * (lane >> 4);
    const int bx_r  = lane & 7;
    const int bx_nt = lane >> 4;
    const int bx_kb = 16 * ((lane >> 3) & 1);

    auto load_stage = [&](int s, int k0) {
        uint32_t base = sbase + s * QKV_STAGE;
#pragma unroll
        for (int it = 0; it < 4; it++) {
            int idx = tid + it * 256;
            int r   = idx >> 3;
            int c   = idx & 7;
            uint32_t off = sw128((uint32_t)(r * 128 + c * 16));
            cp16(base + off,         Ah + (size_t)(brow + r) * K + k0 + c * 8);
            cp16(base + 16384 + off, Al + (size_t)(brow + r) * K + k0 + c * 8);
            cp16(base + 32768 + off, B  + (size_t)(bcol + r) * K + k0 + c * 8);
        }
    };

    const int nch = K >> 6;
    load_stage(0, 0);
    cp_commit();

    for (int c = 0; c < nch; c++) {
        const int s = c & 1;
        if (c + 1 < nch) { load_stage(s ^ 1, (c + 1) << 6); cp_commit(); cp_wait<1>(); }
        else             { cp_wait<0>(); }
        __syncthreads();

        uint32_t base = sbase + s * QKV_STAGE;
#pragma unroll
        for (int ks = 0; ks < 4; ks++) {
            const int kb = ks * 32;
            uint32_t bh[4][2];
#pragma unroll
            for (int ntp = 0; ntp < 2; ntp++) {
                uint32_t off = sw128((uint32_t)((wn + (2*ntp + bx_nt) * 8 + bx_r) * 128 + kb + bx_kb));
                uint32_t r[4];
                ldsm_x4(r, base + 32768 + off);
                bh[2*ntp][0] = r[0]; bh[2*ntp][1] = r[1];
                bh[2*ntp+1][0] = r[2]; bh[2*ntp+1][1] = r[3];
            }
#pragma unroll
            for (int mt = 0; mt < 4; mt++) {
                uint32_t ah[4], al[4];
                uint32_t aoff = sw128((uint32_t)((wm + mt * 16 + a_r) * 128 + kb + a_kb));
                ldsm_x4(ah, base + aoff);
                ldsm_x4(al, base + 16384 + aoff);
#pragma unroll
                for (int nt = 0; nt < 4; nt++) mma16816(acc.a[mt][nt], ah, bh[nt]);
#pragma unroll
                for (int nt = 0; nt < 4; nt++) mma16816(acc.a[mt][nt], al, bh[nt]);
            }
        }
        __syncthreads();
        // (void)s;
    }
}

// Fused QKV projection: grid.x = 24 (0-15 Q | 16-19 K | 20-23 V), grid.y = 16.
__global__ __launch_bounds__(256, 2)
void qkv_gemm(const __half* __restrict__ xh, const __half* __restrict__ xl,
              const __half* __restrict__ wq, const __half* __restrict__ wk,
              const __half* __restrict__ wv,
              __half* __restrict__ q, __half* __restrict__ k, __half* __restrict__ v,
              const float* __restrict__ fc, const float* __restrict__ fs)
{
    extern __shared__ char sm[];
    const uint32_t sbase = smem_u32(sm);
    const int bx   = blockIdx.x;
    const int brow = blockIdx.y * 128;

    const __half* B;
    __half* C;
    int N, bcol, mode;
    if (bx < 16)      { B = wq; C = q; N = DM;  bcol = bx * 128;        mode = 1; }
    else if (bx < 20) { B = wk; C = k; N = KVD; bcol = (bx - 16) * 128; mode = 2; }
    else              { B = wv; C = v; N = KVD; bcol = (bx - 20) * 128; mode = 3; }

    GemmAcc acc;
#pragma unroll
    for (int i = 0; i < 4; i++)
#pragma unroll
        for (int j = 0; j < 4; j++)
#pragma unroll
            for (int e = 0; e < 4; e++) acc.a[i][j][e] = 0.f;

    qkv_mainloop(xh, xl, B, brow, bcol, DM, sbase, acc);

    const int warp = threadIdx.x >> 5;
    const int lane = threadIdx.x & 31;
    const int mrow0 = brow + (warp & 1) * 64 + (lane >> 2);
    const int ncol0 = bcol + (warp >> 1) * 32 + 2 * (lane & 3);
#pragma unroll
    for (int mt = 0; mt < 4; mt++) {
#pragma unroll
        for (int half = 0; half < 2; half++) {
            const int m = mrow0 + mt * 16 + half * 8;
#pragma unroll
            for (int nt = 0; nt < 4; nt++) {
                float v0 = acc.a[mt][nt][half * 2];
                float v1 = acc.a[mt][nt][half * 2 + 1];
                const int n = ncol0 + nt * 8;
                if (mode != 3) {
                    int p = (n & (HD - 1)) >> 1;
                    float cs = fc[m * (HD / 2) + p];
                    float sn = fs[m * (HD / 2) + p];
                    float a = v0, b = v1;
                    v0 = a * cs - b * sn;
                    v1 = a * sn + b * cs;
                    if (mode == 1) { v0 *= 0.125f; v1 *= 0.125f; }
                }
                *(uint32_t*)(C + (size_t)m * N + n) = pack_f16(v0, v1);
            }
        }
    }
}

// ---------------- out GEMM: fp16 3-term (AhBh + AlBh + AhBl), 2-stage ----------
static constexpr int OUT_STAGE = 65536;
static constexpr int OUT_SMEM  = 2 * OUT_STAGE;

__global__ __launch_bounds__(256, 2)
void out_gemm(const __half* __restrict__ Ah, const __half* __restrict__ Al,
              const __half* __restrict__ Bh, const __half* __restrict__ Bl,
              float* __restrict__ C)
{
    extern __shared__ char sm[];
    const uint32_t sbase = smem_u32(sm);
    const int tid  = threadIdx.x;
    const int warp = tid >> 5;
    const int lane = tid & 31;
    const int wm   = (warp & 1) * 64;
    const int wn   = (warp >> 1) * 32;
    const int brow = blockIdx.y * 128;
    const int bcol = blockIdx.x * 128;

    GemmAcc acc;
#pragma unroll
    for (int i = 0; i < 4; i++)
#pragma unroll
        for (int j = 0; j < 4; j++)
#pragma unroll
            for (int e = 0; e < 4; e++) acc.a[i][j][e] = 0.f;

    const int a_r   = (lane & 7) + 8 * ((lane >> 3) & 1);
    const int a_kb  = 16 * (lane >> 4);
    const int bx_r  = lane & 7;
    const int bx_nt = lane >> 4;
    const int bx_kb = 16 * ((lane >> 3) & 1);

    auto load_stage = [&](int s, int k0) {
        uint32_t base = sbase + s * OUT_STAGE;
#pragma unroll
        for (int it = 0; it < 4; it++) {
            int idx = tid + it * 256;
            int r   = idx >> 3;
            int c   = idx & 7;
            uint32_t off = sw128((uint32_t)(r * 128 + c * 16));
            cp16(base + off,         Ah + (size_t)(brow + r) * DM + k0 + c * 8);
            cp16(base + 16384 + off, Al + (size_t)(brow + r) * DM + k0 + c * 8);
            cp16(base + 32768 + off, Bh + (size_t)(bcol + r) * DM + k0 + c * 8);
            cp16(base + 49152 + off, Bl + (size_t)(bcol + r) * DM + k0 + c * 8);
        }
    };

    const int nch = DM >> 6;
    load_stage(0, 0);
    cp_commit();

    for (int c = 0; c < nch; c++) {
        const int s = c & 1;
        if (c + 1 < nch) { load_stage(s ^ 1, (c + 1) << 6); cp_commit(); cp_wait<1>(); }
        else             { cp_wait<0>(); }
        __syncthreads();

        uint32_t base = sbase + s * OUT_STAGE;
#pragma unroll
        for (int ks = 0; ks < 4; ks++) {
            const int kb = ks * 32;
            uint32_t bh[4][2], bl[4][2];
#pragma unroll
            for (int ntp = 0; ntp < 2; ntp++) {
                uint32_t off = sw128((uint32_t)((wn + (2*ntp + bx_nt) * 8 + bx_r) * 128 + kb + bx_kb));
                uint32_t r[4];
                ldsm_x4(r, base + 32768 + off);
                bh[2*ntp][0] = r[0]; bh[2*ntp][1] = r[1];
                bh[2*ntp+1][0] = r[2]; bh[2*ntp+1][1] = r[3];
                ldsm_x4(r, base + 49152 + off);
                bl[2*ntp][0] = r[0]; bl[2*ntp][1] = r[1];
                bl[2*ntp+1][0] = r[2]; bl[2*ntp+1][1] = r[3];
            }
#pragma unroll
            for (int mt = 0; mt < 4; mt++) {
                uint32_t ah[4], al[4];
                uint32_t aoff = sw128((uint32_t)((wm + mt * 16 + a_r) * 128 + kb + a_kb));
                ldsm_x4(ah, base + aoff);
                ldsm_x4(al, base + 16384 + aoff);
#pragma unroll
                for (int nt = 0; nt < 4; nt++) mma16816(acc.a[mt][nt], ah, bh[nt]);
#pragma unroll
                for (int nt = 0; nt < 4; nt++) mma16816(acc.a[mt][nt], al, bh[nt]);
#pragma unroll
                for (int nt = 0; nt < 4; nt++) mma16816(acc.a[mt][nt], ah, bl[nt]);
            }
        }
        __syncthreads();
    }

    const int mrow0 = brow + wm + (lane >> 2);
    const int ncol0 = bcol + wn + 2 * (lane & 3);
#pragma unroll
    for (int mt = 0; mt < 4; mt++) {
#pragma unroll
        for (int half = 0; half < 2; half++) {
            const int m = mrow0 + mt * 16 + half * 8;
#pragma unroll
            for (int nt = 0; nt < 4; nt++) {
                const int n = ncol0 + nt * 8;
                *(float2*)(C + (size_t)m * DM + n) =
                    make_float2(acc.a[mt][nt][half * 2], acc.a[mt][nt][half * 2 + 1]);
            }
        }
    }
}

// ---------------- MMA flash attention: fp16 single-term, 128 q/CTA, 8 warps ----
// smem: Q 16K + 2 stages x (K 8K + V 8K) = 48K.
static constexpr int ATTN_STAGE = 16384;
static constexpr int ATTN_SMEM  = 16384 + 2 * ATTN_STAGE;

__global__ __launch_bounds__(256, 2)
void attn_mma(const __half* __restrict__ Qg, const __half* __restrict__ Kg,
              const __half* __restrict__ Vg,
              __half* __restrict__ Oh, __half* __restrict__ Ol)
{
    extern __shared__ char sm[];
    const uint32_t sb = smem_u32(sm);
    const int tid  = threadIdx.x;
    const int warp = tid >> 5;
    const int lane = tid & 31;
    const int qt   = blockIdx.x;
    const int h    = blockIdx.y;
    const int kvh  = h >> 2;
    const int qb   = qt * 128;

    const uint32_t sQ  = sb;             // 16 KB (128 rows x 128 B)
    const uint32_t st0 = sb + 16384;

    const int kt0   = max(0, (qb - WIN) >> 6);
    const int ktmax = 2 * qt + 1;

#pragma unroll
    for (int it = 0; it < 4; it++) {
        int idx = tid + it * 256;                 // 0..1023
        int r = idx >> 3, c = idx & 7;
        uint32_t off = sw128((uint32_t)(r * 128 + c * 16));
        cp16(sQ + off, Qg + (size_t)(qb + r) * DM + h * HD + c * 8);
    }
    auto load_kv = [&](uint32_t base, int kt) {
#pragma unroll
        for (int it = 0; it < 2; it++) {
            int idx = tid + it * 256;             // 0..511
            int r = idx >> 3, c = idx & 7;
            uint32_t off = sw128((uint32_t)(r * 128 + c * 16));
            size_t go = (size_t)(kt * 64 + r) * KVD + kvh * HD + c * 8;
            cp16(base + off,        Kg + go);
            cp16(base + 8192 + off, Vg + go);
        }
    };
    load_kv(st0, kt0);
    cp_commit();
    cp_wait<0>();
    __syncthreads();

    // Q fragments persistent (16 regs)
    const int a_r  = warp * 16 + (lane & 7) + 8 * ((lane >> 3) & 1);
    const int a_kb = 16 * (lane >> 4);
    uint32_t qf[4][4];
#pragma unroll
    for (int ks = 0; ks < 4; ks++)
        ldsm_x4(qf[ks], sQ + sw128((uint32_t)(a_r * 128 + ks * 32 + a_kb)));

    float O[8][4];
#pragma unroll
    for (int nt = 0; nt < 8; nt++)
#pragma unroll
        for (int e = 0; e < 4; e++) O[nt][e] = 0.f;
    float m0 = -1e20f, m1 = -1e20f, l0 = 0.f, l1 = 0.f;

    const int i0 = qb + warp * 16 + (lane >> 2);
    const int i1 = i0 + 8;
    const int jc = 2 * (lane & 3);
    const int wrow0 = qb + warp * 16;
    const int kx_r  = lane & 7;
    const int kx_nt = lane >> 4;
    const int kx_kb = 16 * ((lane >> 3) & 1);
    const int vx_r  = lane & 15;
    const int vx_nt = lane >> 4;

    for (int kt = kt0; kt <= ktmax; kt++) {
        const int buf = (kt - kt0) & 1;
        if (kt < ktmax) { load_kv(st0 + (buf ^ 1) * ATTN_STAGE, kt + 1); cp_commit(); cp_wait<1>(); }
        else            { cp_wait<0>(); }
        __syncthreads();

        const int ktb = kt * 64;
        const bool act = (ktb <= wrow0 + 15) && (ktb + 63 >= wrow0 - WIN);
        if (act) {
            const uint32_t bK = st0 + buf * ATTN_STAGE;
            const uint32_t bV = bK + 8192;

            float S[8][4];
#pragma unroll
            for (int nt = 0; nt < 8; nt++)
#pragma unroll
                for (int e = 0; e < 4; e++) S[nt][e] = 0.f;

            // ---- S = Q @ K^T (single fp16 term)
#pragma unroll
            for (int ks = 0; ks < 4; ks++) {
                const int kb = ks * 32;
                uint32_t kf[8][2];
#pragma unroll
                for (int ntp = 0; ntp < 4; ntp++) {
                    uint32_t off = sw128((uint32_t)(((2*ntp + kx_nt) * 8 + kx_r) * 128 + kb + kx_kb));
                    uint32_t r[4];
                    ldsm_x4(r, bK + off);
                    kf[2*ntp][0] = r[0]; kf[2*ntp][1] = r[1];
                    kf[2*ntp+1][0] = r[2]; kf[2*ntp+1][1] = r[3];
                }
#pragma unroll
                for (int nt = 0; nt < 8; nt++) mma16816(S[nt], qf[ks], kf[nt]);
            }

            const bool full = (ktb >= qb + 127 - WIN) && (ktb + 64 <= qb);
            if (!full) {
#pragma unroll
                for (int nt = 0; nt < 8; nt++) {
                    int j = ktb + nt * 8 + jc;
                    if (j > i0 || j < i0 - WIN)         S[nt][0] = -1e30f;
                    if (j + 1 > i0 || j + 1 < i0 - WIN) S[nt][1] = -1e30f;
                    if (j > i1 || j < i1 - WIN)         S[nt][2] = -1e30f;
                    if (j + 1 > i1 || j + 1 < i1 - WIN) S[nt][3] = -1e30f;
                }
            }

            float mx0 = -1e30f, mx1 = -1e30f;
#pragma unroll
            for (int nt = 0; nt < 8; nt++) {
                mx0 = fmaxf(mx0, fmaxf(S[nt][0], S[nt][1]));
                mx1 = fmaxf(mx1, fmaxf(S[nt][2], S[nt][3]));
            }
            mx0 = fmaxf(mx0, __shfl_xor_sync(0xffffffffu, mx0, 1));
            mx0 = fmaxf(mx0, __shfl_xor_sync(0xffffffffu, mx0, 2));
            mx1 = fmaxf(mx1, __shfl_xor_sync(0xffffffffu, mx1, 1));
            mx1 = fmaxf(mx1, __shfl_xor_sync(0xffffffffu, mx1, 2));
            const float mn0 = fmaxf(m0, mx0);
            const float mn1 = fmaxf(m1, mx1);
            const bool stable = __all_sync(0xffffffffu, (mn0 == m0) & (mn1 == m1));
            if (!stable) {
                const float sc0 = exp2f((m0 - mn0) * 1.44269504f);
                const float sc1 = exp2f((m1 - mn1) * 1.44269504f);
                m0 = mn0; m1 = mn1;
                l0 *= sc0; l1 *= sc1;
#pragma unroll
                for (int nt = 0; nt < 8; nt++) {
                    O[nt][0] *= sc0; O[nt][1] *= sc0;
                    O[nt][2] *= sc1; O[nt][3] *= sc1;
                }
            }
            float rs0 = 0.f, rs1 = 0.f;
#pragma unroll
            for (int nt = 0; nt < 8; nt++) {
                S[nt][0] = exp2f((S[nt][0] - m0) * 1.44269504f);
                S[nt][1] = exp2f((S[nt][1] - m0) * 1.44269504f);
                S[nt][2] = exp2f((S[nt][2] - m1) * 1.44269504f);
                S[nt][3] = exp2f((S[nt][3] - m1) * 1.44269504f);
                rs0 += S[nt][0] + S[nt][1];
                rs1 += S[nt][2] + S[nt][3];
            }
            rs0 += __shfl_xor_sync(0xffffffffu, rs0, 1);
            rs0 += __shfl_xor_sync(0xffffffffu, rs0, 2);
            rs1 += __shfl_xor_sync(0xffffffffu, rs1, 1);
            rs1 += __shfl_xor_sync(0xffffffffu, rs1, 2);
            l0 += rs0; l1 += rs1;

            // ---- pack P single fp16
            uint32_t pa[4][4];
#pragma unroll
            for (int ks = 0; ks < 4; ks++) {
                pa[ks][0] = pack_f16(S[2*ks][0],   S[2*ks][1]);
                pa[ks][1] = pack_f16(S[2*ks][2],   S[2*ks][3]);
                pa[ks][2] = pack_f16(S[2*ks+1][0], S[2*ks+1][1]);
                pa[ks][3] = pack_f16(S[2*ks+1][2], S[2*ks+1][3]);
            }

            // ---- O += P @ V (single fp16 term)
#pragma unroll
            for (int ks = 0; ks < 4; ks++) {
                uint32_t vf[8][2];
#pragma unroll
                for (int ntp = 0; ntp < 4; ntp++) {
                    uint32_t off = sw128((uint32_t)((ks * 16 + vx_r) * 128 + (2*ntp + vx_nt) * 16));
                    uint32_t r[4];
                    ldsm_x4t(r, bV + off);
                    vf[2*ntp][0] = r[0]; vf[2*ntp][1] = r[1];
                    vf[2*ntp+1][0] = r[2]; vf[2*ntp+1][1] = r[3];
                }
#pragma unroll
                for (int nt = 0; nt < 8; nt++) mma16816(O[nt], pa[ks], vf[nt]);
            }
        }
        __syncthreads();
    }

    const float inv0 = 1.f / l0;
    const float inv1 = 1.f / l1;
    const int row0 = qb + warp * 16 + (lane >> 2);
    const int colb = h * HD + jc;
#pragma unroll
    for (int nt = 0; nt < 8; nt++) {
        uint32_t hp, lp;
        split2h(O[nt][0] * inv0, O[nt][1] * inv0, hp, lp);
        size_t o = (size_t)row0 * DM + colb + nt * 8;
        *(uint32_t*)(Oh + o) = hp;
        *(uint32_t*)(Ol + o) = lp;
        split2h(O[nt][2] * inv1, O[nt][3] * inv1, hp, lp);
        o += (size_t)8 * DM;
        *(uint32_t*)(Oh + o) = hp;
        *(uint32_t*)(Ol + o) = lp;
    }
}

// ---------------- launch --------------------------------------------------------
extern "C" void kernel_launch(void* const* d_in, const int* in_sizes, int n_in,
                              void* d_out, int out_size)
{
    const float* x  = (const float*)d_in[0];
    const float* wq = (const float*)d_in[1];
    const float* wk = (const float*)d_in[2];
    const float* wv = (const float*)d_in[3];
    const float* wo = (const float*)d_in[4];
    const float* fc = (const float*)d_in[5];
    const float* fs = (const float*)d_in[6];
    float* out = (float*)d_out;

    __half *xh, *xl, *twq, *twk, *twv, *twoh, *twol, *q, *k, *v, *aoh, *aol;
    cudaGetSymbolAddress((void**)&xh,   g_xh);  cudaGetSymbolAddress((void**)&xl,   g_xl);
    cudaGetSymbolAddress((void**)&twq,  g_wq);  cudaGetSymbolAddress((void**)&twk,  g_wk);
    cudaGetSymbolAddress((void**)&twv,  g_wv);
    cudaGetSymbolAddress((void**)&twoh, g_woh); cudaGetSymbolAddress((void**)&twol, g_wol);
    cudaGetSymbolAddress((void**)&q,    g_Q);   cudaGetSymbolAddress((void**)&k,    g_K);
    cudaGetSymbolAddress((void**)&v,    g_V);
    cudaGetSymbolAddress((void**)&aoh,  g_aoh); cudaGetSymbolAddress((void**)&aol,  g_aol);

    cudaFuncSetAttribute(qkv_gemm, cudaFuncAttributeMaxDynamicSharedMemorySize, QKV_SMEM);
    cudaFuncSetAttribute(out_gemm, cudaFuncAttributeMaxDynamicSharedMemorySize, OUT_SMEM);
    cudaFuncSetAttribute(attn_mma, cudaFuncAttributeMaxDynamicSharedMemorySize, ATTN_SMEM);

    const int n4 = SQ * DM / 4;
    split_kernel<<<n4 / 256, 256>>>(x, xh, xl, n4);
    transpose_all<<<5120, 256>>>(wq, wk, wv, wo, twq, twk, twv, twoh, twol);

    qkv_gemm<<<dim3(24, 16), 256, QKV_SMEM>>>(xh, xl, twq, twk, twv, q, k, v, fc, fs);

    attn_mma<<<dim3(SQ / 128, NH), 256, ATTN_SMEM>>>(q, k, v, aoh, aol);

    out_gemm<<<dim3(16, 16), 256, OUT_SMEM>>>(aoh, aol, twoh, twol, out);
}

// round 10
// speedup vs baseline: 1.6766x; 1.1762x over previous
#include <cuda_runtime.h>
#include <cuda_fp16.h>
#include <math.h>
#include <stdint.h>

#define SQ 2048
#define DM 2048
#define NH 32
#define NKV 8
#define HD 64
#define WIN 1024
#define KVD (NKV*HD)

// ---------------- scratch (device globals) -----------------------------------
__device__ __half g_xh [SQ*DM],  g_xl [SQ*DM];
__device__ __half g_wq [DM*DM];                 // [N][K] single fp16
__device__ __half g_wk [KVD*DM];
__device__ __half g_wv [KVD*DM];
__device__ __half g_wo [DM*DM];                 // single fp16
__device__ __half g_Q  [SQ*DM];                 // rope'd, scaled
__device__ __half g_K  [SQ*KVD];                // rope'd
__device__ __half g_V  [SQ*KVD];
__device__ __half g_aoh[SQ*DM], g_aol[SQ*DM];   // attention out, 2-term

// ---------------- helpers -----------------------------------------------------
__device__ __forceinline__ uint32_t smem_u32(const void* p) {
    uint32_t a;
    asm("{ .reg .u64 t; cvta.to.shared.u64 t, %1; cvt.u32.u64 %0, t; }" : "=r"(a) : "l"(p));
    return a;
}
__device__ __forceinline__ void cp16(uint32_t s, const void* g) {
    asm volatile("cp.async.cg.shared.global [%0], [%1], 16;" :: "r"(s), "l"(g));
}
__device__ __forceinline__ void cp_commit() { asm volatile("cp.async.commit_group;" ::: "memory"); }
template<int N> __device__ __forceinline__ void cp_wait() {
    asm volatile("cp.async.wait_group %0;" :: "n"(N) : "memory");
}
__device__ __forceinline__ void ldsm_x4(uint32_t* r, uint32_t addr) {
    asm volatile("ldmatrix.sync.aligned.m8n8.x4.shared.b16 {%0,%1,%2,%3}, [%4];"
                 : "=r"(r[0]), "=r"(r[1]), "=r"(r[2]), "=r"(r[3]) : "r"(addr));
}
__device__ __forceinline__ void ldsm_x4t(uint32_t* r, uint32_t addr) {
    asm volatile("ldmatrix.sync.aligned.m8n8.x4.trans.shared.b16 {%0,%1,%2,%3}, [%4];"
                 : "=r"(r[0]), "=r"(r[1]), "=r"(r[2]), "=r"(r[3]) : "r"(addr));
}
__device__ __forceinline__ void mma16816(float* c, const uint32_t* a, const uint32_t* b) {
    asm volatile("mma.sync.aligned.m16n8k16.row.col.f32.f16.f16.f32 "
                 "{%0,%1,%2,%3}, {%4,%5,%6,%7}, {%8,%9}, {%0,%1,%2,%3};"
                 : "+f"(c[0]), "+f"(c[1]), "+f"(c[2]), "+f"(c[3])
                 : "r"(a[0]), "r"(a[1]), "r"(a[2]), "r"(a[3]), "r"(b[0]), "r"(b[1]));
}
__device__ __forceinline__ uint32_t pack_f16(float lo, float hi) {
    uint32_t r;
    asm("cvt.rn.f16x2.f32 %0, %1, %2;" : "=r"(r) : "f"(hi), "f"(lo));
    return r;
}
__device__ __forceinline__ void split2h(float v0, float v1, uint32_t& hp, uint32_t& lp) {
    hp = pack_f16(v0, v1);
    __half2 h = *reinterpret_cast<__half2*>(&hp);
    float f0 = __half2float(__low2half(h));
    float f1 = __half2float(__high2half(h));
    lp = pack_f16(v0 - f0, v1 - f1);
}

// ---------------- fused pre-pass: x split + 4 weight transposes ----------------
// blocks [0,4096): x split (256 float4/block). blocks [4096,9216): transposes.
__device__ __forceinline__ void t_tile1(const float* __restrict__ W, __half* __restrict__ T,
                                        int K, int N, int tile, float (*t)[33])
{
    const int tid = threadIdx.x;
    const int ntn = N >> 5;
    const int k0 = (tile / ntn) << 6;
    const int n0 = (tile % ntn) << 5;
#pragma unroll
    for (int it = 0; it < 8; it++) {
        int idx = tid + it * 256;
        int r = idx >> 5, c = idx & 31;
        t[r][c] = W[(size_t)(k0 + r) * N + n0 + c];
    }
    __syncthreads();
    const int n  = tid >> 3;
    const int kk = tid & 7;
#pragma unroll
    for (int it = 0; it < 4; it++) {
        int kp = kk + it * 8;
        *(uint32_t*)(T + (size_t)(n0 + n) * K + k0 + 2 * kp) =
            pack_f16(t[2*kp][n], t[2*kp+1][n]);
    }
}

__global__ __launch_bounds__(256)
void prepass_all(const float* __restrict__ x,
                 const float* __restrict__ wq, const float* __restrict__ wk,
                 const float* __restrict__ wv, const float* __restrict__ wo,
                 __half* xh, __half* xl,
                 __half* twq, __half* twk, __half* twv, __half* two)
{
    __shared__ float t[64][33];
    int b = blockIdx.x;
    if (b < 4096) {
        int i = b * 256 + threadIdx.x;
        float4 v = ((const float4*)x)[i];
        uint32_t h0, l0, h1, l1;
        split2h(v.x, v.y, h0, l0);
        split2h(v.z, v.w, h1, l1);
        ((uint32_t*)xh)[2*i] = h0; ((uint32_t*)xh)[2*i+1] = h1;
        ((uint32_t*)xl)[2*i] = l0; ((uint32_t*)xl)[2*i+1] = l1;
        return;
    }
    b -= 4096;
    if (b < 2048)        t_tile1(wq, twq, DM, DM,  b,        t);
    else if (b < 2560)   t_tile1(wk, twk, DM, KVD, b - 2048, t);
    else if (b < 3072)   t_tile1(wv, twv, DM, KVD, b - 2560, t);
    else                 t_tile1(wo, two, DM, DM,  b - 3072, t);
}

// ---------------- GEMM mainloop: fp16 2-term (A hi/lo x B), 2-stage, 128x128 ---
// smem/stage: A_h 16K + A_l 16K + B 16K = 48K; 2 stages = 96K.
static constexpr int GEMM_STAGE = 49152;
static constexpr int GEMM_SMEM  = 2 * GEMM_STAGE;

struct GemmAcc { float a[4][4][4]; };

__device__ __forceinline__ void gemm_mainloop(
    const __half* __restrict__ Ah, const __half* __restrict__ Al,
    const __half* __restrict__ B,
    int brow, int bcol, int K, uint32_t sbase, GemmAcc& acc)
{
    const int tid  = threadIdx.x;
    const int warp = tid >> 5;
    const int lane = tid & 31;
    const int wm   = (warp & 1) * 64;
    const int wn   = (warp >> 1) * 32;

    // ldmatrix addressing (closed-form swizzle: col ^ ((row&7)<<4))
    const int xo    = (lane & 7) << 4;                      // (row&7)<<4 for A and B
    const int a_row = wm + (lane & 7) + 8 * ((lane >> 3) & 1);
    const int a_kb  = 16 * (lane >> 4);
    const int b_row = wn + (lane >> 4) * 8 + (lane & 7);    // + 16*ntp below
    const int b_kb  = 16 * ((lane >> 3) & 1);

    // cp.async store addressing: per-thread constant column
    const int ld_r0  = tid >> 3;
    const uint32_t ld_col = (uint32_t)(((tid & 7) * 16) ^ (((tid >> 3) & 7) << 4));

    auto load_stage = [&](int s, int k0) {
        uint32_t base = sbase + s * GEMM_STAGE;
#pragma unroll
        for (int it = 0; it < 4; it++) {
            int r = ld_r0 + it * 32;
            uint32_t off = (uint32_t)(r * 128) + ld_col;
            const int ke = (tid & 7) * 8;
            cp16(base + off,         Ah + (size_t)(brow + r) * K + k0 + ke);
            cp16(base + 16384 + off, Al + (size_t)(brow + r) * K + k0 + ke);
            cp16(base + 32768 + off, B  + (size_t)(bcol + r) * K + k0 + ke);
        }
    };

    const int nch = K >> 6;
    load_stage(0, 0);
    cp_commit();

    for (int c = 0; c < nch; c++) {
        const int s = c & 1;
        if (c + 1 < nch) { load_stage(s ^ 1, (c + 1) << 6); cp_commit(); cp_wait<1>(); }
        else             { cp_wait<0>(); }
        __syncthreads();

        uint32_t base = sbase + s * GEMM_STAGE;
#pragma unroll
        for (int ks = 0; ks < 4; ks++) {
            const int kb = ks * 32;
            const uint32_t acol = (uint32_t)((kb + a_kb) ^ xo);
            const uint32_t bcol2 = (uint32_t)((kb + b_kb) ^ xo);
            uint32_t bh[4][2];
#pragma unroll
            for (int ntp = 0; ntp < 2; ntp++) {
                uint32_t addr = base + 32768 + (uint32_t)((b_row + ntp * 16) * 128) + bcol2;
                uint32_t r[4];
                ldsm_x4(r, addr);
                bh[2*ntp][0] = r[0]; bh[2*ntp][1] = r[1];
                bh[2*ntp+1][0] = r[2]; bh[2*ntp+1][1] = r[3];
            }
#pragma unroll
            for (int mt = 0; mt < 4; mt++) {
                uint32_t ah[4], al[4];
                uint32_t arow = (uint32_t)((a_row + mt * 16) * 128);
                ldsm_x4(ah, base + arow + acol);
                ldsm_x4(al, base + 16384 + arow + acol);
#pragma unroll
                for (int nt = 0; nt < 4; nt++) mma16816(acc.a[mt][nt], ah, bh[nt]);
#pragma unroll
                for (int nt = 0; nt < 4; nt++) mma16816(acc.a[mt][nt], al, bh[nt]);
            }
        }
        __syncthreads();
    }
}

// Fused QKV projection: grid.x = 24 (0-15 Q | 16-19 K | 20-23 V), grid.y = 16.
__global__ __launch_bounds__(256, 2)
void qkv_gemm(const __half* __restrict__ xh, const __half* __restrict__ xl,
              const __half* __restrict__ wq, const __half* __restrict__ wk,
              const __half* __restrict__ wv,
              __half* __restrict__ q, __half* __restrict__ k, __half* __restrict__ v,
              const float* __restrict__ fc, const float* __restrict__ fs)
{
    extern __shared__ char sm[];
    const uint32_t sbase = smem_u32(sm);
    const int bx   = blockIdx.x;
    const int brow = blockIdx.y * 128;

    const __half* B;
    __half* C;
    int N, bcol, mode;
    if (bx < 16)      { B = wq; C = q; N = DM;  bcol = bx * 128;        mode = 1; }
    else if (bx < 20) { B = wk; C = k; N = KVD; bcol = (bx - 16) * 128; mode = 2; }
    else              { B = wv; C = v; N = KVD; bcol = (bx - 20) * 128; mode = 3; }

    GemmAcc acc;
#pragma unroll
    for (int i = 0; i < 4; i++)
#pragma unroll
        for (int j = 0; j < 4; j++)
#pragma unroll
            for (int e = 0; e < 4; e++) acc.a[i][j][e] = 0.f;

    gemm_mainloop(xh, xl, B, brow, bcol, DM, sbase, acc);

    const int warp = threadIdx.x >> 5;
    const int lane = threadIdx.x & 31;
    const int mrow0 = brow + (warp & 1) * 64 + (lane >> 2);
    const int ncol0 = bcol + (warp >> 1) * 32 + 2 * (lane & 3);
#pragma unroll
    for (int mt = 0; mt < 4; mt++) {
#pragma unroll
        for (int half = 0; half < 2; half++) {
            const int m = mrow0 + mt * 16 + half * 8;
#pragma unroll
            for (int nt = 0; nt < 4; nt++) {
                float v0 = acc.a[mt][nt][half * 2];
                float v1 = acc.a[mt][nt][half * 2 + 1];
                const int n = ncol0 + nt * 8;
                if (mode != 3) {
                    int p = (n & (HD - 1)) >> 1;
                    float cs = fc[m * (HD / 2) + p];
                    float sn = fs[m * (HD / 2) + p];
                    float a = v0, b = v1;
                    v0 = a * cs - b * sn;
                    v1 = a * sn + b * cs;
                    if (mode == 1) { v0 *= 0.125f; v1 *= 0.125f; }
                }
                *(uint32_t*)(C + (size_t)m * N + n) = pack_f16(v0, v1);
            }
        }
    }
}

// Output projection: AO (hi/lo) @ wo (single fp16), fp32 out.
__global__ __launch_bounds__(256, 2)
void out_gemm(const __half* __restrict__ Ah, const __half* __restrict__ Al,
              const __half* __restrict__ B, float* __restrict__ C)
{
    extern __shared__ char sm[];
    const uint32_t sbase = smem_u32(sm);
    const int brow = blockIdx.y * 128;
    const int bcol = blockIdx.x * 128;

    GemmAcc acc;
#pragma unroll
    for (int i = 0; i < 4; i++)
#pragma unroll
        for (int j = 0; j < 4; j++)
#pragma unroll
            for (int e = 0; e < 4; e++) acc.a[i][j][e] = 0.f;

    gemm_mainloop(Ah, Al, B, brow, bcol, DM, sbase, acc);

    const int warp = threadIdx.x >> 5;
    const int lane = threadIdx.x & 31;
    const int mrow0 = brow + (warp & 1) * 64 + (lane >> 2);
    const int ncol0 = bcol + (warp >> 1) * 32 + 2 * (lane & 3);
#pragma unroll
    for (int mt = 0; mt < 4; mt++) {
#pragma unroll
        for (int half = 0; half < 2; half++) {
            const int m = mrow0 + mt * 16 + half * 8;
#pragma unroll
            for (int nt = 0; nt < 4; nt++) {
                const int n = ncol0 + nt * 8;
                *(float2*)(C + (size_t)m * DM + n) =
                    make_float2(acc.a[mt][nt][half * 2], acc.a[mt][nt][half * 2 + 1]);
            }
        }
    }
}

// ---------------- MMA flash attention: fp16 single-term, 128 q/CTA, 8 warps ----
// smem: Q 16K + 2 stages x (K 8K + V 8K) = 48K.
static constexpr int ATTN_STAGE = 16384;
static constexpr int ATTN_SMEM  = 16384 + 2 * ATTN_STAGE;

__global__ __launch_bounds__(256, 2)
void attn_mma(const __half* __restrict__ Qg, const __half* __restrict__ Kg,
              const __half* __restrict__ Vg,
              __half* __restrict__ Oh, __half* __restrict__ Ol)
{
    extern __shared__ char sm[];
    const uint32_t sb = smem_u32(sm);
    const int tid  = threadIdx.x;
    const int warp = tid >> 5;
    const int lane = tid & 31;
    const int qt   = blockIdx.x;
    const int h    = blockIdx.y;
    const int kvh  = h >> 2;
    const int qb   = qt * 128;

    const uint32_t sQ  = sb;             // 16 KB
    const uint32_t st0 = sb + 16384;

    const int kt0   = max(0, (qb - WIN) >> 6);
    const int ktmax = 2 * qt + 1;

    // cp.async addressing (per-thread constant column)
    const int ld_r0 = tid >> 3;
    const uint32_t ld_col = (uint32_t)(((tid & 7) * 16) ^ (((tid >> 3) & 7) << 4));
    const int ld_ke = (tid & 7) * 8;

#pragma unroll
    for (int it = 0; it < 4; it++) {
        int r = ld_r0 + it * 32;
        uint32_t off = (uint32_t)(r * 128) + ld_col;
        cp16(sQ + off, Qg + (size_t)(qb + r) * DM + h * HD + ld_ke);
    }
    auto load_kv = [&](uint32_t base, int kt) {
#pragma unroll
        for (int it = 0; it < 2; it++) {
            int r = ld_r0 + it * 32;
            uint32_t off = (uint32_t)(r * 128) + ld_col;
            size_t go = (size_t)(kt * 64 + r) * KVD + kvh * HD + ld_ke;
            cp16(base + off,        Kg + go);
            cp16(base + 8192 + off, Vg + go);
        }
    };
    load_kv(st0, kt0);
    cp_commit();
    cp_wait<0>();
    __syncthreads();

    // Q fragments persistent; closed-form swizzle addressing
    const int qxor  = (lane & 7) << 4;
    const int q_row = warp * 16 + (lane & 7) + 8 * ((lane >> 3) & 1);
    const int q_kb  = 16 * (lane >> 4);
    uint32_t qf[4][4];
#pragma unroll
    for (int ks = 0; ks < 4; ks++)
        ldsm_x4(qf[ks], sQ + (uint32_t)(q_row * 128) + (uint32_t)((ks * 32 + q_kb) ^ qxor));

    float O[8][4];
#pragma unroll
    for (int nt = 0; nt < 8; nt++)
#pragma unroll
        for (int e = 0; e < 4; e++) O[nt][e] = 0.f;
    float m0 = -1e20f, m1 = -1e20f, l0 = 0.f, l1 = 0.f;

    const int i0 = qb + warp * 16 + (lane >> 2);
    const int i1 = i0 + 8;
    const int jc = 2 * (lane & 3);
    const int wrow0 = qb + warp * 16;
    // K frag addressing: row = (2ntp + (lane>>4))*8 + (lane&7)
    const uint32_t krow = (uint32_t)(((lane >> 4) * 8 + (lane & 7)) * 128);
    const int kxor = (lane & 7) << 4;
    const int k_kb = 16 * ((lane >> 3) & 1);
    // V frag addressing: row = ks*16 + (lane&15); col = (2ntp + (lane>>4))*16
    const uint32_t vrow = (uint32_t)((lane & 15) * 128);
    const int vxor = (lane & 7) << 4;
    const int v_cb = (lane >> 4) * 16;

    for (int kt = kt0; kt <= ktmax; kt++) {
        const int buf = (kt - kt0) & 1;
        if (kt < ktmax) { load_kv(st0 + (buf ^ 1) * ATTN_STAGE, kt + 1); cp_commit(); cp_wait<1>(); }
        else            { cp_wait<0>(); }
        __syncthreads();

        const int ktb = kt * 64;
        const bool act = (ktb <= wrow0 + 15) && (ktb + 63 >= wrow0 - WIN);
        if (act) {
            const uint32_t bK = st0 + buf * ATTN_STAGE;
            const uint32_t bV = bK + 8192;

            float S[8][4];
#pragma unroll
            for (int nt = 0; nt < 8; nt++)
#pragma unroll
                for (int e = 0; e < 4; e++) S[nt][e] = 0.f;

            // ---- S = Q @ K^T
#pragma unroll
            for (int ks = 0; ks < 4; ks++) {
                const uint32_t kcol = (uint32_t)((ks * 32 + k_kb) ^ kxor);
                uint32_t kf[8][2];
#pragma unroll
                for (int ntp = 0; ntp < 4; ntp++) {
                    uint32_t r[4];
                    ldsm_x4(r, bK + krow + (uint32_t)(ntp * 2048) + kcol);
                    kf[2*ntp][0] = r[0]; kf[2*ntp][1] = r[1];
                    kf[2*ntp+1][0] = r[2]; kf[2*ntp+1][1] = r[3];
                }
#pragma unroll
                for (int nt = 0; nt < 8; nt++) mma16816(S[nt], qf[ks], kf[nt]);
            }

            const bool full = (ktb >= qb + 127 - WIN) && (ktb + 64 <= qb);
            if (!full) {
#pragma unroll
                for (int nt = 0; nt < 8; nt++) {
                    int j = ktb + nt * 8 + jc;
                    if (j > i0 || j < i0 - WIN)         S[nt][0] = -1e30f;
                    if (j + 1 > i0 || j + 1 < i0 - WIN) S[nt][1] = -1e30f;
                    if (j > i1 || j < i1 - WIN)         S[nt][2] = -1e30f;
                    if (j + 1 > i1 || j + 1 < i1 - WIN) S[nt][3] = -1e30f;
                }
            }

            float mx0 = -1e30f, mx1 = -1e30f;
#pragma unroll
            for (int nt = 0; nt < 8; nt++) {
                mx0 = fmaxf(mx0, fmaxf(S[nt][0], S[nt][1]));
                mx1 = fmaxf(mx1, fmaxf(S[nt][2], S[nt][3]));
            }
            mx0 = fmaxf(mx0, __shfl_xor_sync(0xffffffffu, mx0, 1));
            mx0 = fmaxf(mx0, __shfl_xor_sync(0xffffffffu, mx0, 2));
            mx1 = fmaxf(mx1, __shfl_xor_sync(0xffffffffu, mx1, 1));
            mx1 = fmaxf(mx1, __shfl_xor_sync(0xffffffffu, mx1, 2));
            const float mn0 = fmaxf(m0, mx0);
            const float mn1 = fmaxf(m1, mx1);
            const bool stable = __all_sync(0xffffffffu, (mn0 == m0) & (mn1 == m1));
            if (!stable) {
                const float sc0 = exp2f((m0 - mn0) * 1.44269504f);
                const float sc1 = exp2f((m1 - mn1) * 1.44269504f);
                m0 = mn0; m1 = mn1;
                l0 *= sc0; l1 *= sc1;
#pragma unroll
                for (int nt = 0; nt < 8; nt++) {
                    O[nt][0] *= sc0; O[nt][1] *= sc0;
                    O[nt][2] *= sc1; O[nt][3] *= sc1;
                }
            }
            float rs0 = 0.f, rs1 = 0.f;
#pragma unroll
            for (int nt = 0; nt < 8; nt++) {
                S[nt][0] = exp2f((S[nt][0] - m0) * 1.44269504f);
                S[nt][1] = exp2f((S[nt][1] - m0) * 1.44269504f);
                S[nt][2] = exp2f((S[nt][2] - m1) * 1.44269504f);
                S[nt][3] = exp2f((S[nt][3] - m1) * 1.44269504f);
                rs0 += S[nt][0] + S[nt][1];
                rs1 += S[nt][2] + S[nt][3];
            }
            rs0 += __shfl_xor_sync(0xffffffffu, rs0, 1);
            rs0 += __shfl_xor_sync(0xffffffffu, rs0, 2);
            rs1 += __shfl_xor_sync(0xffffffffu, rs1, 1);
            rs1 += __shfl_xor_sync(0xffffffffu, rs1, 2);
            l0 += rs0; l1 += rs1;

            // ---- pack P single fp16
            uint32_t pa[4][4];
#pragma unroll
            for (int ks = 0; ks < 4; ks++) {
                pa[ks][0] = pack_f16(S[2*ks][0],   S[2*ks][1]);
                pa[ks][1] = pack_f16(S[2*ks][2],   S[2*ks][3]);
                pa[ks][2] = pack_f16(S[2*ks+1][0], S[2*ks+1][1]);
                pa[ks][3] = pack_f16(S[2*ks+1][2], S[2*ks+1][3]);
            }

            // ---- O += P @ V
#pragma unroll
            for (int ks = 0; ks < 4; ks++) {
                const uint32_t vbase = bV + vrow + (uint32_t)(ks * 2048);
                uint32_t vf[8][2];
#pragma unroll
                for (int ntp = 0; ntp < 4; ntp++) {
                    uint32_t r[4];
                    ldsm_x4t(r, vbase + (uint32_t)((ntp * 32 + v_cb) ^ vxor));
                    vf[2*ntp][0] = r[0]; vf[2*ntp][1] = r[1];
                    vf[2*ntp+1][0] = r[2]; vf[2*ntp+1][1] = r[3];
                }
#pragma unroll
                for (int nt = 0; nt < 8; nt++) mma16816(O[nt], pa[ks], vf[nt]);
            }
        }
        __syncthreads();
    }

    const float inv0 = 1.f / l0;
    const float inv1 = 1.f / l1;
    const int row0 = qb + warp * 16 + (lane >> 2);
    const int colb = h * HD + jc;
#pragma unroll
    for (int nt = 0; nt < 8; nt++) {
        uint32_t hp, lp;
        split2h(O[nt][0] * inv0, O[nt][1] * inv0, hp, lp);
        size_t o = (size_t)row0 * DM + colb + nt * 8;
        *(uint32_t*)(Oh + o) = hp;
        *(uint32_t*)(Ol + o) = lp;
        split2h(O[nt][2] * inv1, O[nt][3] * inv1, hp, lp);
        o += (size_t)8 * DM;
        *(uint32_t*)(Oh + o) = hp;
        *(uint32_t*)(Ol + o) = lp;
    }
}

// ---------------- launch --------------------------------------------------------
extern "C" void kernel_launch(void* const* d_in, const int* in_sizes, int n_in,
                              void* d_out, int out_size)
{
    const float* x  = (const float*)d_in[0];
    const float* wq = (const float*)d_in[1];
    const float* wk = (const float*)d_in[2];
    const float* wv = (const float*)d_in[3];
    const float* wo = (const float*)d_in[4];
    const float* fc = (const float*)d_in[5];
    const float* fs = (const float*)d_in[6];
    float* out = (float*)d_out;

    __half *xh, *xl, *twq, *twk, *twv, *two, *q, *k, *v, *aoh, *aol;
    cudaGetSymbolAddress((void**)&xh,  g_xh);  cudaGetSymbolAddress((void**)&xl,  g_xl);
    cudaGetSymbolAddress((void**)&twq, g_wq);  cudaGetSymbolAddress((void**)&twk, g_wk);
    cudaGetSymbolAddress((void**)&twv, g_wv);  cudaGetSymbolAddress((void**)&two, g_wo);
    cudaGetSymbolAddress((void**)&q,   g_Q);   cudaGetSymbolAddress((void**)&k,   g_K);
    cudaGetSymbolAddress((void**)&v,   g_V);
    cudaGetSymbolAddress((void**)&aoh, g_aoh); cudaGetSymbolAddress((void**)&aol, g_aol);

    cudaFuncSetAttribute(qkv_gemm, cudaFuncAttributeMaxDynamicSharedMemorySize, GEMM_SMEM);
    cudaFuncSetAttribute(out_gemm, cudaFuncAttributeMaxDynamicSharedMemorySize, GEMM_SMEM);
    cudaFuncSetAttribute(attn_mma, cudaFuncAttributeMaxDynamicSharedMemorySize, ATTN_SMEM);

    prepass_all<<<9216, 256>>>(x, wq, wk, wv, wo, xh, xl, twq, twk, twv, two);

    qkv_gemm<<<dim3(24, 16), 256, GEMM_SMEM>>>(xh, xl, twq, twk, twv, q, k, v, fc, fs);

    attn_mma<<<dim3(SQ / 128, NH), 256, ATTN_SMEM>>>(q, k, v, aoh, aol);

    out_gemm<<<dim3(16, 16), 256, GEMM_SMEM>>>(aoh, aol, two, out);
}

// round 11
// speedup vs baseline: 2.4895x; 1.4848x over previous
#include <cuda_runtime.h>
#include <cuda_fp16.h>
#include <math.h>
#include <stdint.h>

#define SQ 2048
#define DM 2048
#define NH 32
#define NKV 8
#define HD 64
#define WIN 1024
#define KVD (NKV*HD)

// ---------------- scratch (device globals) -----------------------------------
__device__ __half g_x  [SQ*DM];                 // x single fp16
__device__ __half g_wq [DM*DM];                 // [N][K] single fp16
__device__ __half g_wk [KVD*DM];
__device__ __half g_wv [KVD*DM];
__device__ __half g_wo [DM*DM];
__device__ __half g_Q  [SQ*DM];                 // rope'd, scaled
__device__ __half g_K  [SQ*KVD];                // rope'd
__device__ __half g_V  [SQ*KVD];
__device__ __half g_AO [SQ*DM];                 // attention out single fp16

// ---------------- helpers -----------------------------------------------------
__device__ __forceinline__ uint32_t smem_u32(const void* p) {
    uint32_t a;
    asm("{ .reg .u64 t; cvta.to.shared.u64 t, %1; cvt.u32.u64 %0, t; }" : "=r"(a) : "l"(p));
    return a;
}
__device__ __forceinline__ void cp16(uint32_t s, const void* g) {
    asm volatile("cp.async.cg.shared.global [%0], [%1], 16;" :: "r"(s), "l"(g));
}
__device__ __forceinline__ void cp_commit() { asm volatile("cp.async.commit_group;" ::: "memory"); }
template<int N> __device__ __forceinline__ void cp_wait() {
    asm volatile("cp.async.wait_group %0;" :: "n"(N) : "memory");
}
__device__ __forceinline__ void ldsm_x4(uint32_t* r, uint32_t addr) {
    asm volatile("ldmatrix.sync.aligned.m8n8.x4.shared.b16 {%0,%1,%2,%3}, [%4];"
                 : "=r"(r[0]), "=r"(r[1]), "=r"(r[2]), "=r"(r[3]) : "r"(addr));
}
__device__ __forceinline__ void ldsm_x4t(uint32_t* r, uint32_t addr) {
    asm volatile("ldmatrix.sync.aligned.m8n8.x4.trans.shared.b16 {%0,%1,%2,%3}, [%4];"
                 : "=r"(r[0]), "=r"(r[1]), "=r"(r[2]), "=r"(r[3]) : "r"(addr));
}
__device__ __forceinline__ void mma16816(float* c, const uint32_t* a, const uint32_t* b) {
    asm volatile("mma.sync.aligned.m16n8k16.row.col.f32.f16.f16.f32 "
                 "{%0,%1,%2,%3}, {%4,%5,%6,%7}, {%8,%9}, {%0,%1,%2,%3};"
                 : "+f"(c[0]), "+f"(c[1]), "+f"(c[2]), "+f"(c[3])
                 : "r"(a[0]), "r"(a[1]), "r"(a[2]), "r"(a[3]), "r"(b[0]), "r"(b[1]));
}
__device__ __forceinline__ uint32_t pack_f16(float lo, float hi) {
    uint32_t r;
    asm("cvt.rn.f16x2.f32 %0, %1, %2;" : "=r"(r) : "f"(hi), "f"(lo));
    return r;
}

// ---------------- fused pre-pass: x convert + 4 weight transposes --------------
// blocks [0,2048): x convert (512 float4/block). blocks [2048,7168): transposes.
__device__ __forceinline__ void t_tile1(const float* __restrict__ W, __half* __restrict__ T,
                                        int K, int N, int tile, float (*t)[33])
{
    const int tid = threadIdx.x;
    const int ntn = N >> 5;
    const int k0 = (tile / ntn) << 6;
    const int n0 = (tile % ntn) << 5;
#pragma unroll
    for (int it = 0; it < 8; it++) {
        int idx = tid + it * 256;
        int r = idx >> 5, c = idx & 31;
        t[r][c] = W[(size_t)(k0 + r) * N + n0 + c];
    }
    __syncthreads();
    const int n  = tid >> 3;
    const int kk = tid & 7;
#pragma unroll
    for (int it = 0; it < 4; it++) {
        int kp = kk + it * 8;
        *(uint32_t*)(T + (size_t)(n0 + n) * K + k0 + 2 * kp) =
            pack_f16(t[2*kp][n], t[2*kp+1][n]);
    }
}

__global__ __launch_bounds__(256)
void prepass_all(const float* __restrict__ x,
                 const float* __restrict__ wq, const float* __restrict__ wk,
                 const float* __restrict__ wv, const float* __restrict__ wo,
                 __half* xo,
                 __half* twq, __half* twk, __half* twv, __half* two)
{
    __shared__ float t[64][33];
    int b = blockIdx.x;
    if (b < 2048) {
#pragma unroll
        for (int it = 0; it < 2; it++) {
            int i = b * 512 + it * 256 + threadIdx.x;
            float4 v = ((const float4*)x)[i];
            ((uint2*)xo)[i] = make_uint2(pack_f16(v.x, v.y), pack_f16(v.z, v.w));
        }
        return;
    }
    b -= 2048;
    if (b < 2048)        t_tile1(wq, twq, DM, DM,  b,        t);
    else if (b < 2560)   t_tile1(wk, twk, DM, KVD, b - 2048, t);
    else if (b < 3072)   t_tile1(wv, twv, DM, KVD, b - 2560, t);
    else                 t_tile1(wo, two, DM, DM,  b - 3072, t);
}

// ---------------- GEMM mainloop: fp16 single-term, 3-stage, 128x128, BK=64 -----
// smem/stage: A 16K + B 16K = 32K; 3 stages = 96K.
static constexpr int GEMM_STAGE = 32768;
static constexpr int GEMM_SMEM  = 3 * GEMM_STAGE;

struct GemmAcc { float a[4][4][4]; };

__device__ __forceinline__ void gemm_mainloop(
    const __half* __restrict__ A, const __half* __restrict__ B,
    int brow, int bcol, int K, uint32_t sbase, GemmAcc& acc)
{
    const int tid  = threadIdx.x;
    const int warp = tid >> 5;
    const int lane = tid & 31;
    const int wm   = (warp & 1) * 64;
    const int wn   = (warp >> 1) * 32;

    const int xo    = (lane & 7) << 4;
    const int a_row = wm + (lane & 7) + 8 * ((lane >> 3) & 1);
    const int a_kb  = 16 * (lane >> 4);
    const int b_row = wn + (lane >> 4) * 8 + (lane & 7);
    const int b_kb  = 16 * ((lane >> 3) & 1);

    const int ld_r0 = tid >> 3;
    const uint32_t ld_col = (uint32_t)(((tid & 7) * 16) ^ (((tid >> 3) & 7) << 4));
    const int ld_ke = (tid & 7) * 8;

    auto load_stage = [&](int s, int k0) {
        uint32_t base = sbase + s * GEMM_STAGE;
#pragma unroll
        for (int it = 0; it < 4; it++) {
            int r = ld_r0 + it * 32;
            uint32_t off = (uint32_t)(r * 128) + ld_col;
            cp16(base + off,         A + (size_t)(brow + r) * K + k0 + ld_ke);
            cp16(base + 16384 + off, B + (size_t)(bcol + r) * K + k0 + ld_ke);
        }
    };

    const int nch = K >> 6;
    load_stage(0, 0);  cp_commit();
    load_stage(1, 64); cp_commit();

    int s = 0;
    for (int c = 0; c < nch; c++) {
        if (c + 2 < nch) load_stage((s + 2 >= 3) ? s - 1 : s + 2, (c + 2) << 6);
        cp_commit();
        cp_wait<2>();
        __syncthreads();

        uint32_t base = sbase + s * GEMM_STAGE;
#pragma unroll
        for (int ks = 0; ks < 4; ks++) {
            const int kb = ks * 32;
            const uint32_t acol  = (uint32_t)((kb + a_kb) ^ xo);
            const uint32_t bcol2 = (uint32_t)((kb + b_kb) ^ xo);
            uint32_t bh[4][2];
#pragma unroll
            for (int ntp = 0; ntp < 2; ntp++) {
                uint32_t r[4];
                ldsm_x4(r, base + 16384 + (uint32_t)((b_row + ntp * 16) * 128) + bcol2);
                bh[2*ntp][0] = r[0]; bh[2*ntp][1] = r[1];
                bh[2*ntp+1][0] = r[2]; bh[2*ntp+1][1] = r[3];
            }
#pragma unroll
            for (int mt = 0; mt < 4; mt++) {
                uint32_t ah[4];
                ldsm_x4(ah, base + (uint32_t)((a_row + mt * 16) * 128) + acol);
#pragma unroll
                for (int nt = 0; nt < 4; nt++) mma16816(acc.a[mt][nt], ah, bh[nt]);
            }
        }
        __syncthreads();
        s = (s + 1 >= 3) ? 0 : s + 1;
    }
}

// Fused QKV projection: grid.x = 24 (0-15 Q | 16-19 K | 20-23 V), grid.y = 16.
__global__ __launch_bounds__(256, 2)
void qkv_gemm(const __half* __restrict__ x,
              const __half* __restrict__ wq, const __half* __restrict__ wk,
              const __half* __restrict__ wv,
              __half* __restrict__ q, __half* __restrict__ k, __half* __restrict__ v,
              const float* __restrict__ fc, const float* __restrict__ fs)
{
    extern __shared__ char sm[];
    const uint32_t sbase = smem_u32(sm);
    const int bx   = blockIdx.x;
    const int brow = blockIdx.y * 128;

    const __half* B;
    __half* C;
    int N, bcol, mode;
    if (bx < 16)      { B = wq; C = q; N = DM;  bcol = bx * 128;        mode = 1; }
    else if (bx < 20) { B = wk; C = k; N = KVD; bcol = (bx - 16) * 128; mode = 2; }
    else              { B = wv; C = v; N = KVD; bcol = (bx - 20) * 128; mode = 3; }

    GemmAcc acc;
#pragma unroll
    for (int i = 0; i < 4; i++)
#pragma unroll
        for (int j = 0; j < 4; j++)
#pragma unroll
            for (int e = 0; e < 4; e++) acc.a[i][j][e] = 0.f;

    gemm_mainloop(x, B, brow, bcol, DM, sbase, acc);

    const int warp = threadIdx.x >> 5;
    const int lane = threadIdx.x & 31;
    const int mrow0 = brow + (warp & 1) * 64 + (lane >> 2);
    const int ncol0 = bcol + (warp >> 1) * 32 + 2 * (lane & 3);
#pragma unroll
    for (int mt = 0; mt < 4; mt++) {
#pragma unroll
        for (int half = 0; half < 2; half++) {
            const int m = mrow0 + mt * 16 + half * 8;
#pragma unroll
            for (int nt = 0; nt < 4; nt++) {
                float v0 = acc.a[mt][nt][half * 2];
                float v1 = acc.a[mt][nt][half * 2 + 1];
                const int n = ncol0 + nt * 8;
                if (mode != 3) {
                    int p = (n & (HD - 1)) >> 1;
                    float cs = fc[m * (HD / 2) + p];
                    float sn = fs[m * (HD / 2) + p];
                    float a = v0, b = v1;
                    v0 = a * cs - b * sn;
                    v1 = a * sn + b * cs;
                    if (mode == 1) { v0 *= 0.125f; v1 *= 0.125f; }
                }
                *(uint32_t*)(C + (size_t)m * N + n) = pack_f16(v0, v1);
            }
        }
    }
}

// Output projection: AO (single fp16) @ wo (single fp16), fp32 out.
__global__ __launch_bounds__(256, 2)
void out_gemm(const __half* __restrict__ A, const __half* __restrict__ B,
              float* __restrict__ C)
{
    extern __shared__ char sm[];
    const uint32_t sbase = smem_u32(sm);
    const int brow = blockIdx.y * 128;
    const int bcol = blockIdx.x * 128;

    GemmAcc acc;
#pragma unroll
    for (int i = 0; i < 4; i++)
#pragma unroll
        for (int j = 0; j < 4; j++)
#pragma unroll
            for (int e = 0; e < 4; e++) acc.a[i][j][e] = 0.f;

    gemm_mainloop(A, B, brow, bcol, DM, sbase, acc);

    const int warp = threadIdx.x >> 5;
    const int lane = threadIdx.x & 31;
    const int mrow0 = brow + (warp & 1) * 64 + (lane >> 2);
    const int ncol0 = bcol + (warp >> 1) * 32 + 2 * (lane & 3);
#pragma unroll
    for (int mt = 0; mt < 4; mt++) {
#pragma unroll
        for (int half = 0; half < 2; half++) {
            const int m = mrow0 + mt * 16 + half * 8;
#pragma unroll
            for (int nt = 0; nt < 4; nt++) {
                const int n = ncol0 + nt * 8;
                *(float2*)(C + (size_t)m * DM + n) =
                    make_float2(acc.a[mt][nt][half * 2], acc.a[mt][nt][half * 2 + 1]);
            }
        }
    }
}

// ---------------- MMA flash attention: fp16 single-term, 128 q/CTA, 8 warps ----
static constexpr int ATTN_STAGE = 16384;
static constexpr int ATTN_SMEM  = 16384 + 2 * ATTN_STAGE;

__global__ __launch_bounds__(256, 2)
void attn_mma(const __half* __restrict__ Qg, const __half* __restrict__ Kg,
              const __half* __restrict__ Vg, __half* __restrict__ O_out)
{
    extern __shared__ char sm[];
    const uint32_t sb = smem_u32(sm);
    const int tid  = threadIdx.x;
    const int warp = tid >> 5;
    const int lane = tid & 31;
    const int qt   = blockIdx.x;
    const int h    = blockIdx.y;
    const int kvh  = h >> 2;
    const int qb   = qt * 128;

    const uint32_t sQ  = sb;
    const uint32_t st0 = sb + 16384;

    const int kt0   = max(0, (qb - WIN) >> 6);
    const int ktmax = 2 * qt + 1;

    const int ld_r0 = tid >> 3;
    const uint32_t ld_col = (uint32_t)(((tid & 7) * 16) ^ (((tid >> 3) & 7) << 4));
    const int ld_ke = (tid & 7) * 8;

#pragma unroll
    for (int it = 0; it < 4; it++) {
        int r = ld_r0 + it * 32;
        cp16(sQ + (uint32_t)(r * 128) + ld_col, Qg + (size_t)(qb + r) * DM + h * HD + ld_ke);
    }
    auto load_kv = [&](uint32_t base, int kt) {
#pragma unroll
        for (int it = 0; it < 2; it++) {
            int r = ld_r0 + it * 32;
            uint32_t off = (uint32_t)(r * 128) + ld_col;
            size_t go = (size_t)(kt * 64 + r) * KVD + kvh * HD + ld_ke;
            cp16(base + off,        Kg + go);
            cp16(base + 8192 + off, Vg + go);
        }
    };
    load_kv(st0, kt0);
    cp_commit();
    cp_wait<0>();
    __syncthreads();

    const int qxor  = (lane & 7) << 4;
    const int q_row = warp * 16 + (lane & 7) + 8 * ((lane >> 3) & 1);
    const int q_kb  = 16 * (lane >> 4);
    uint32_t qf[4][4];
#pragma unroll
    for (int ks = 0; ks < 4; ks++)
        ldsm_x4(qf[ks], sQ + (uint32_t)(q_row * 128) + (uint32_t)((ks * 32 + q_kb) ^ qxor));

    float O[8][4];
#pragma unroll
    for (int nt = 0; nt < 8; nt++)
#pragma unroll
        for (int e = 0; e < 4; e++) O[nt][e] = 0.f;
    float m0 = -1e20f, m1 = -1e20f, l0 = 0.f, l1 = 0.f;

    const int i0 = qb + warp * 16 + (lane >> 2);
    const int i1 = i0 + 8;
    const int jc = 2 * (lane & 3);
    const int wrow0 = qb + warp * 16;
    const uint32_t krow = (uint32_t)(((lane >> 4) * 8 + (lane & 7)) * 128);
    const int kxor = (lane & 7) << 4;
    const int k_kb = 16 * ((lane >> 3) & 1);
    const uint32_t vrow = (uint32_t)((lane & 15) * 128);
    const int vxor = (lane & 7) << 4;
    const int v_cb = (lane >> 4) * 16;

    for (int kt = kt0; kt <= ktmax; kt++) {
        const int buf = (kt - kt0) & 1;
        if (kt < ktmax) { load_kv(st0 + (buf ^ 1) * ATTN_STAGE, kt + 1); cp_commit(); cp_wait<1>(); }
        else            { cp_wait<0>(); }
        __syncthreads();

        const int ktb = kt * 64;
        const bool act = (ktb <= wrow0 + 15) && (ktb + 63 >= wrow0 - WIN);
        if (act) {
            const uint32_t bK = st0 + buf * ATTN_STAGE;
            const uint32_t bV = bK + 8192;

            float S[8][4];
#pragma unroll
            for (int nt = 0; nt < 8; nt++)
#pragma unroll
                for (int e = 0; e < 4; e++) S[nt][e] = 0.f;

#pragma unroll
            for (int ks = 0; ks < 4; ks++) {
                const uint32_t kcol = (uint32_t)((ks * 32 + k_kb) ^ kxor);
                uint32_t kf[8][2];
#pragma unroll
                for (int ntp = 0; ntp < 4; ntp++) {
                    uint32_t r[4];
                    ldsm_x4(r, bK + krow + (uint32_t)(ntp * 2048) + kcol);
                    kf[2*ntp][0] = r[0]; kf[2*ntp][1] = r[1];
                    kf[2*ntp+1][0] = r[2]; kf[2*ntp+1][1] = r[3];
                }
#pragma unroll
                for (int nt = 0; nt < 8; nt++) mma16816(S[nt], qf[ks], kf[nt]);
            }

            const bool full = (ktb >= qb + 127 - WIN) && (ktb + 64 <= qb);
            if (!full) {
#pragma unroll
                for (int nt = 0; nt < 8; nt++) {
                    int j = ktb + nt * 8 + jc;
                    if (j > i0 || j < i0 - WIN)         S[nt][0] = -1e30f;
                    if (j + 1 > i0 || j + 1 < i0 - WIN) S[nt][1] = -1e30f;
                    if (j > i1 || j < i1 - WIN)         S[nt][2] = -1e30f;
                    if (j + 1 > i1 || j + 1 < i1 - WIN) S[nt][3] = -1e30f;
                }
            }

            float mx0 = -1e30f, mx1 = -1e30f;
#pragma unroll
            for (int nt = 0; nt < 8; nt++) {
                mx0 = fmaxf(mx0, fmaxf(S[nt][0], S[nt][1]));
                mx1 = fmaxf(mx1, fmaxf(S[nt][2], S[nt][3]));
            }
            mx0 = fmaxf(mx0, __shfl_xor_sync(0xffffffffu, mx0, 1));
            mx0 = fmaxf(mx0, __shfl_xor_sync(0xffffffffu, mx0, 2));
            mx1 = fmaxf(mx1, __shfl_xor_sync(0xffffffffu, mx1, 1));
            mx1 = fmaxf(mx1, __shfl_xor_sync(0xffffffffu, mx1, 2));
            const float mn0 = fmaxf(m0, mx0);
            const float mn1 = fmaxf(m1, mx1);
            const bool stable = __all_sync(0xffffffffu, (mn0 == m0) & (mn1 == m1));
            if (!stable) {
                const float sc0 = exp2f((m0 - mn0) * 1.44269504f);
                const float sc1 = exp2f((m1 - mn1) * 1.44269504f);
                m0 = mn0; m1 = mn1;
                l0 *= sc0; l1 *= sc1;
#pragma unroll
                for (int nt = 0; nt < 8; nt++) {
                    O[nt][0] *= sc0; O[nt][1] *= sc0;
                    O[nt][2] *= sc1; O[nt][3] *= sc1;
                }
            }
            float rs0 = 0.f, rs1 = 0.f;
#pragma unroll
            for (int nt = 0; nt < 8; nt++) {
                S[nt][0] = exp2f((S[nt][0] - m0) * 1.44269504f);
                S[nt][1] = exp2f((S[nt][1] - m0) * 1.44269504f);
                S[nt][2] = exp2f((S[nt][2] - m1) * 1.44269504f);
                S[nt][3] = exp2f((S[nt][3] - m1) * 1.44269504f);
                rs0 += S[nt][0] + S[nt][1];
                rs1 += S[nt][2] + S[nt][3];
            }
            rs0 += __shfl_xor_sync(0xffffffffu, rs0, 1);
            rs0 += __shfl_xor_sync(0xffffffffu, rs0, 2);
            rs1 += __shfl_xor_sync(0xffffffffu, rs1, 1);
            rs1 += __shfl_xor_sync(0xffffffffu, rs1, 2);
            l0 += rs0; l1 += rs1;

            uint32_t pa[4][4];
#pragma unroll
            for (int ks = 0; ks < 4; ks++) {
                pa[ks][0] = pack_f16(S[2*ks][0],   S[2*ks][1]);
                pa[ks][1] = pack_f16(S[2*ks][2],   S[2*ks][3]);
                pa[ks][2] = pack_f16(S[2*ks+1][0], S[2*ks+1][1]);
                pa[ks][3] = pack_f16(S[2*ks+1][2], S[2*ks+1][3]);
            }

#pragma unroll
            for (int ks = 0; ks < 4; ks++) {
                const uint32_t vbase = bV + vrow + (uint32_t)(ks * 2048);
                uint32_t vf[8][2];
#pragma unroll
                for (int ntp = 0; ntp < 4; ntp++) {
                    uint32_t r[4];
                    ldsm_x4t(r, vbase + (uint32_t)((ntp * 32 + v_cb) ^ vxor));
                    vf[2*ntp][0] = r[0]; vf[2*ntp][1] = r[1];
                    vf[2*ntp+1][0] = r[2]; vf[2*ntp+1][1] = r[3];
                }
#pragma unroll
                for (int nt = 0; nt < 8; nt++) mma16816(O[nt], pa[ks], vf[nt]);
            }
        }
        __syncthreads();
    }

    const float inv0 = 1.f / l0;
    const float inv1 = 1.f / l1;
    const int row0 = qb + warp * 16 + (lane >> 2);
    const int colb = h * HD + jc;
#pragma unroll
    for (int nt = 0; nt < 8; nt++) {
        size_t o = (size_t)row0 * DM + colb + nt * 8;
        *(uint32_t*)(O_out + o) = pack_f16(O[nt][0] * inv0, O[nt][1] * inv0);
        o += (size_t)8 * DM;
        *(uint32_t*)(O_out + o) = pack_f16(O[nt][2] * inv1, O[nt][3] * inv1);
    }
}

// ---------------- launch --------------------------------------------------------
extern "C" void kernel_launch(void* const* d_in, const int* in_sizes, int n_in,
                              void* d_out, int out_size)
{
    const float* x  = (const float*)d_in[0];
    const float* wq = (const float*)d_in[1];
    const float* wk = (const float*)d_in[2];
    const float* wv = (const float*)d_in[3];
    const float* wo = (const float*)d_in[4];
    const float* fc = (const float*)d_in[5];
    const float* fs = (const float*)d_in[6];
    float* out = (float*)d_out;

    __half *xp, *twq, *twk, *twv, *two, *q, *k, *v, *ao;
    cudaGetSymbolAddress((void**)&xp,  g_x);
    cudaGetSymbolAddress((void**)&twq, g_wq);  cudaGetSymbolAddress((void**)&twk, g_wk);
    cudaGetSymbolAddress((void**)&twv, g_wv);  cudaGetSymbolAddress((void**)&two, g_wo);
    cudaGetSymbolAddress((void**)&q,   g_Q);   cudaGetSymbolAddress((void**)&k,   g_K);
    cudaGetSymbolAddress((void**)&v,   g_V);   cudaGetSymbolAddress((void**)&ao,  g_AO);

    cudaFuncSetAttribute(qkv_gemm, cudaFuncAttributeMaxDynamicSharedMemorySize, GEMM_SMEM);
    cudaFuncSetAttribute(out_gemm, cudaFuncAttributeMaxDynamicSharedMemorySize, GEMM_SMEM);
    cudaFuncSetAttribute(attn_mma, cudaFuncAttributeMaxDynamicSharedMemorySize, ATTN_SMEM);

    prepass_all<<<7168, 256>>>(x, wq, wk, wv, wo, xp, twq, twk, twv, two);

    qkv_gemm<<<dim3(24, 16), 256, GEMM_SMEM>>>(xp, twq, twk, twv, q, k, v, fc, fs);

    attn_mma<<<dim3(SQ / 128, NH), 256, ATTN_SMEM>>>(q, k, v, ao);

    out_gemm<<<dim3(16, 16), 256, GEMM_SMEM>>>(ao, two, out);
}

// round 12
// speedup vs baseline: 2.5163x; 1.0108x over previous
#include <cuda_runtime.h>
#include <cuda_fp16.h>
#include <math.h>
#include <stdint.h>

#define SQ 2048
#define DM 2048
#define NH 32
#define NKV 8
#define HD 64
#define WIN 1024
#define KVD (NKV*HD)

// ---------------- scratch (device globals) -----------------------------------
__device__ __half g_x  [SQ*DM];
__device__ __half g_wq [DM*DM];                 // [N][K]
__device__ __half g_wk [KVD*DM];
__device__ __half g_wv [KVD*DM];
__device__ __half g_wo [DM*DM];
__device__ __half g_Q  [SQ*DM];
__device__ __half g_K  [SQ*KVD];
__device__ __half g_V  [SQ*KVD];
__device__ __half g_AO [SQ*DM];

// ---------------- helpers -----------------------------------------------------
__device__ __forceinline__ uint32_t smem_u32(const void* p) {
    uint32_t a;
    asm("{ .reg .u64 t; cvta.to.shared.u64 t, %1; cvt.u32.u64 %0, t; }" : "=r"(a) : "l"(p));
    return a;
}
__device__ __forceinline__ void cp16(uint32_t s, const void* g) {
    asm volatile("cp.async.cg.shared.global [%0], [%1], 16;" :: "r"(s), "l"(g));
}
__device__ __forceinline__ void cp_commit() { asm volatile("cp.async.commit_group;" ::: "memory"); }
template<int N> __device__ __forceinline__ void cp_wait() {
    asm volatile("cp.async.wait_group %0;" :: "n"(N) : "memory");
}
__device__ __forceinline__ void ldsm_x4(uint32_t* r, uint32_t addr) {
    asm volatile("ldmatrix.sync.aligned.m8n8.x4.shared.b16 {%0,%1,%2,%3}, [%4];"
                 : "=r"(r[0]), "=r"(r[1]), "=r"(r[2]), "=r"(r[3]) : "r"(addr));
}
__device__ __forceinline__ void ldsm_x4t(uint32_t* r, uint32_t addr) {
    asm volatile("ldmatrix.sync.aligned.m8n8.x4.trans.shared.b16 {%0,%1,%2,%3}, [%4];"
                 : "=r"(r[0]), "=r"(r[1]), "=r"(r[2]), "=r"(r[3]) : "r"(addr));
}
__device__ __forceinline__ void mma16816(float* c, const uint32_t* a, const uint32_t* b) {
    asm volatile("mma.sync.aligned.m16n8k16.row.col.f32.f16.f16.f32 "
                 "{%0,%1,%2,%3}, {%4,%5,%6,%7}, {%8,%9}, {%0,%1,%2,%3};"
                 : "+f"(c[0]), "+f"(c[1]), "+f"(c[2]), "+f"(c[3])
                 : "r"(a[0]), "r"(a[1]), "r"(a[2]), "r"(a[3]), "r"(b[0]), "r"(b[1]));
}
__device__ __forceinline__ uint32_t pack_f16(float lo, float hi) {
    uint32_t r;
    asm("cvt.rn.f16x2.f32 %0, %1, %2;" : "=r"(r) : "f"(hi), "f"(lo));
    return r;
}

// ---------------- weight transpose tile (shared by prepass + attn tail) --------
__device__ __forceinline__ void t_tile1(const float* __restrict__ W, __half* __restrict__ T,
                                        int K, int N, int tile, float (*t)[33])
{
    const int tid = threadIdx.x;
    const int ntn = N >> 5;
    const int k0 = (tile / ntn) << 6;
    const int n0 = (tile % ntn) << 5;
#pragma unroll
    for (int it = 0; it < 8; it++) {
        int idx = tid + it * 256;
        int r = idx >> 5, c = idx & 31;
        t[r][c] = W[(size_t)(k0 + r) * N + n0 + c];
    }
    __syncthreads();
    const int n  = tid >> 3;
    const int kk = tid & 7;
#pragma unroll
    for (int it = 0; it < 4; it++) {
        int kp = kk + it * 8;
        *(uint32_t*)(T + (size_t)(n0 + n) * K + k0 + 2 * kp) =
            pack_f16(t[2*kp][n], t[2*kp+1][n]);
    }
}

// ---------------- pre-pass: x convert + wq/wk/wv transposes --------------------
__global__ __launch_bounds__(256)
void prepass_all(const float* __restrict__ x,
                 const float* __restrict__ wq, const float* __restrict__ wk,
                 const float* __restrict__ wv,
                 __half* xo, __half* twq, __half* twk, __half* twv)
{
    __shared__ float t[64][33];
    int b = blockIdx.x;
    if (b < 2048) {
#pragma unroll
        for (int it = 0; it < 2; it++) {
            int i = b * 512 + it * 256 + threadIdx.x;
            float4 v = ((const float4*)x)[i];
            ((uint2*)xo)[i] = make_uint2(pack_f16(v.x, v.y), pack_f16(v.z, v.w));
        }
        return;
    }
    b -= 2048;
    if (b < 2048)        t_tile1(wq, twq, DM, DM,  b,        t);
    else if (b < 2560)   t_tile1(wk, twk, DM, KVD, b - 2048, t);
    else                 t_tile1(wv, twv, DM, KVD, b - 2560, t);
}

// ---------------- GEMM mainloop: fp16 single-term, 3-stage, 1 sync/chunk -------
static constexpr int GEMM_STAGE = 32768;
static constexpr int GEMM_SMEM  = 3 * GEMM_STAGE;

struct GemmAcc { float a[4][4][4]; };

__device__ __forceinline__ void gemm_mainloop(
    const __half* __restrict__ A, const __half* __restrict__ B,
    int brow, int bcol, int K, uint32_t sbase, GemmAcc& acc)
{
    const int tid  = threadIdx.x;
    const int warp = tid >> 5;
    const int lane = tid & 31;
    const int wm   = (warp & 1) * 64;
    const int wn   = (warp >> 1) * 32;

    const int xo    = (lane & 7) << 4;
    const int a_row = wm + (lane & 7) + 8 * ((lane >> 3) & 1);
    const int a_kb  = 16 * (lane >> 4);
    const int b_row = wn + (lane >> 4) * 8 + (lane & 7);
    const int b_kb  = 16 * ((lane >> 3) & 1);

    const int ld_r0 = tid >> 3;
    const uint32_t ld_col = (uint32_t)(((tid & 7) * 16) ^ (((tid >> 3) & 7) << 4));
    const int ld_ke = (tid & 7) * 8;

    auto load_stage = [&](int s, int k0) {
        uint32_t base = sbase + s * GEMM_STAGE;
#pragma unroll
        for (int it = 0; it < 4; it++) {
            int r = ld_r0 + it * 32;
            uint32_t off = (uint32_t)(r * 128) + ld_col;
            cp16(base + off,         A + (size_t)(brow + r) * K + k0 + ld_ke);
            cp16(base + 16384 + off, B + (size_t)(bcol + r) * K + k0 + ld_ke);
        }
    };

    const int nch = K >> 6;
    load_stage(0, 0);  cp_commit();
    load_stage(1, 64); cp_commit();

    int s = 0;
    for (int c = 0; c < nch; c++) {
        cp_wait<1>();
        __syncthreads();                 // single barrier per chunk
        if (c + 2 < nch) load_stage((s + 2 >= 3) ? s - 1 : s + 2, (c + 2) << 6);
        cp_commit();                     // possibly empty (tail)

        uint32_t base = sbase + s * GEMM_STAGE;
#pragma unroll
        for (int ks = 0; ks < 4; ks++) {
            const int kb = ks * 32;
            const uint32_t acol  = (uint32_t)((kb + a_kb) ^ xo);
            const uint32_t bcol2 = (uint32_t)((kb + b_kb) ^ xo);
            uint32_t bh[4][2];
#pragma unroll
            for (int ntp = 0; ntp < 2; ntp++) {
                uint32_t r[4];
                ldsm_x4(r, base + 16384 + (uint32_t)((b_row + ntp * 16) * 128) + bcol2);
                bh[2*ntp][0] = r[0]; bh[2*ntp][1] = r[1];
                bh[2*ntp+1][0] = r[2]; bh[2*ntp+1][1] = r[3];
            }
#pragma unroll
            for (int mt = 0; mt < 4; mt++) {
                uint32_t ah[4];
                ldsm_x4(ah, base + (uint32_t)((a_row + mt * 16) * 128) + acol);
#pragma unroll
                for (int nt = 0; nt < 4; nt++) mma16816(acc.a[mt][nt], ah, bh[nt]);
            }
        }
        s = (s + 1 >= 3) ? 0 : s + 1;
    }
}

// Fused QKV projection
__global__ __launch_bounds__(256, 2)
void qkv_gemm(const __half* __restrict__ x,
              const __half* __restrict__ wq, const __half* __restrict__ wk,
              const __half* __restrict__ wv,
              __half* __restrict__ q, __half* __restrict__ k, __half* __restrict__ v,
              const float* __restrict__ fc, const float* __restrict__ fs)
{
    extern __shared__ char sm[];
    const uint32_t sbase = smem_u32(sm);
    const int bx   = blockIdx.x;
    const int brow = blockIdx.y * 128;

    const __half* B;
    __half* C;
    int N, bcol, mode;
    if (bx < 16)      { B = wq; C = q; N = DM;  bcol = bx * 128;        mode = 1; }
    else if (bx < 20) { B = wk; C = k; N = KVD; bcol = (bx - 16) * 128; mode = 2; }
    else              { B = wv; C = v; N = KVD; bcol = (bx - 20) * 128; mode = 3; }

    GemmAcc acc;
#pragma unroll
    for (int i = 0; i < 4; i++)
#pragma unroll
        for (int j = 0; j < 4; j++)
#pragma unroll
            for (int e = 0; e < 4; e++) acc.a[i][j][e] = 0.f;

    gemm_mainloop(x, B, brow, bcol, DM, sbase, acc);

    const int warp = threadIdx.x >> 5;
    const int lane = threadIdx.x & 31;
    const int mrow0 = brow + (warp & 1) * 64 + (lane >> 2);
    const int ncol0 = bcol + (warp >> 1) * 32 + 2 * (lane & 3);
#pragma unroll
    for (int mt = 0; mt < 4; mt++) {
#pragma unroll
        for (int half = 0; half < 2; half++) {
            const int m = mrow0 + mt * 16 + half * 8;
#pragma unroll
            for (int nt = 0; nt < 4; nt++) {
                float v0 = acc.a[mt][nt][half * 2];
                float v1 = acc.a[mt][nt][half * 2 + 1];
                const int n = ncol0 + nt * 8;
                if (mode != 3) {
                    int p = (n & (HD - 1)) >> 1;
                    float cs = fc[m * (HD / 2) + p];
                    float sn = fs[m * (HD / 2) + p];
                    float a = v0, b = v1;
                    v0 = a * cs - b * sn;
                    v1 = a * sn + b * cs;
                    if (mode == 1) { v0 *= 0.125f; v1 *= 0.125f; }
                }
                *(uint32_t*)(C + (size_t)m * N + n) = pack_f16(v0, v1);
            }
        }
    }
}

// Output projection
__global__ __launch_bounds__(256, 2)
void out_gemm(const __half* __restrict__ A, const __half* __restrict__ B,
              float* __restrict__ C)
{
    extern __shared__ char sm[];
    const uint32_t sbase = smem_u32(sm);
    const int brow = blockIdx.y * 128;
    const int bcol = blockIdx.x * 128;

    GemmAcc acc;
#pragma unroll
    for (int i = 0; i < 4; i++)
#pragma unroll
        for (int j = 0; j < 4; j++)
#pragma unroll
            for (int e = 0; e < 4; e++) acc.a[i][j][e] = 0.f;

    gemm_mainloop(A, B, brow, bcol, DM, sbase, acc);

    const int warp = threadIdx.x >> 5;
    const int lane = threadIdx.x & 31;
    const int mrow0 = brow + (warp & 1) * 64 + (lane >> 2);
    const int ncol0 = bcol + (warp >> 1) * 32 + 2 * (lane & 3);
#pragma unroll
    for (int mt = 0; mt < 4; mt++) {
#pragma unroll
        for (int half = 0; half < 2; half++) {
            const int m = mrow0 + mt * 16 + half * 8;
#pragma unroll
            for (int nt = 0; nt < 4; nt++) {
                const int n = ncol0 + nt * 8;
                *(float2*)(C + (size_t)m * DM + n) =
                    make_float2(acc.a[mt][nt][half * 2], acc.a[mt][nt][half * 2 + 1]);
            }
        }
    }
}

// ---------------- MMA flash attention + fused wo transpose tail ----------------
static constexpr int ATTN_STAGE = 16384;
static constexpr int ATTN_SMEM  = 16384 + 2 * ATTN_STAGE;

__global__ __launch_bounds__(256, 2)
void attn_mma(const __half* __restrict__ Qg, const __half* __restrict__ Kg,
              const __half* __restrict__ Vg, __half* __restrict__ O_out,
              const float* __restrict__ wo, __half* __restrict__ two)
{
    extern __shared__ char sm[];
    const uint32_t sb = smem_u32(sm);
    const int tid  = threadIdx.x;
    const int warp = tid >> 5;
    const int lane = tid & 31;
    const int qt   = blockIdx.x;
    const int h    = blockIdx.y;
    const int kvh  = h >> 2;
    const int qb   = qt * 128;

    const uint32_t sQ  = sb;
    const uint32_t st0 = sb + 16384;

    const int kt0   = max(0, (qb - WIN) >> 6);
    const int ktmax = 2 * qt + 1;

    const int ld_r0 = tid >> 3;
    const uint32_t ld_col = (uint32_t)(((tid & 7) * 16) ^ (((tid >> 3) & 7) << 4));
    const int ld_ke = (tid & 7) * 8;

#pragma unroll
    for (int it = 0; it < 4; it++) {
        int r = ld_r0 + it * 32;
        cp16(sQ + (uint32_t)(r * 128) + ld_col, Qg + (size_t)(qb + r) * DM + h * HD + ld_ke);
    }
    auto load_kv = [&](uint32_t base, int kt) {
#pragma unroll
        for (int it = 0; it < 2; it++) {
            int r = ld_r0 + it * 32;
            uint32_t off = (uint32_t)(r * 128) + ld_col;
            size_t go = (size_t)(kt * 64 + r) * KVD + kvh * HD + ld_ke;
            cp16(base + off,        Kg + go);
            cp16(base + 8192 + off, Vg + go);
        }
    };
    load_kv(st0, kt0);
    cp_commit();
    cp_wait<0>();
    __syncthreads();

    const int qxor  = (lane & 7) << 4;
    const int q_row = warp * 16 + (lane & 7) + 8 * ((lane >> 3) & 1);
    const int q_kb  = 16 * (lane >> 4);
    uint32_t qf[4][4];
#pragma unroll
    for (int ks = 0; ks < 4; ks++)
        ldsm_x4(qf[ks], sQ + (uint32_t)(q_row * 128) + (uint32_t)((ks * 32 + q_kb) ^ qxor));

    float O[8][4];
#pragma unroll
    for (int nt = 0; nt < 8; nt++)
#pragma unroll
        for (int e = 0; e < 4; e++) O[nt][e] = 0.f;
    float m0 = -1e20f, m1 = -1e20f, l0 = 0.f, l1 = 0.f;

    const int i0 = qb + warp * 16 + (lane >> 2);
    const int i1 = i0 + 8;
    const int jc = 2 * (lane & 3);
    const int wrow0 = qb + warp * 16;
    const uint32_t krow = (uint32_t)(((lane >> 4) * 8 + (lane & 7)) * 128);
    const int kxor = (lane & 7) << 4;
    const int k_kb = 16 * ((lane >> 3) & 1);
    const uint32_t vrow = (uint32_t)((lane & 15) * 128);
    const int vxor = (lane & 7) << 4;
    const int v_cb = (lane >> 4) * 16;

    for (int kt = kt0; kt <= ktmax; kt++) {
        const int buf = (kt - kt0) & 1;
        cp_wait<0>();
        __syncthreads();                 // single barrier per tile
        if (kt < ktmax) load_kv(st0 + (buf ^ 1) * ATTN_STAGE, kt + 1);
        cp_commit();

        const int ktb = kt * 64;
        const bool act = (ktb <= wrow0 + 15) && (ktb + 63 >= wrow0 - WIN);
        if (act) {
            const uint32_t bK = st0 + buf * ATTN_STAGE;
            const uint32_t bV = bK + 8192;

            float S[8][4];
#pragma unroll
            for (int nt = 0; nt < 8; nt++)
#pragma unroll
                for (int e = 0; e < 4; e++) S[nt][e] = 0.f;

#pragma unroll
            for (int ks = 0; ks < 4; ks++) {
                const uint32_t kcol = (uint32_t)((ks * 32 + k_kb) ^ kxor);
                uint32_t kf[8][2];
#pragma unroll
                for (int ntp = 0; ntp < 4; ntp++) {
                    uint32_t r[4];
                    ldsm_x4(r, bK + krow + (uint32_t)(ntp * 2048) + kcol);
                    kf[2*ntp][0] = r[0]; kf[2*ntp][1] = r[1];
                    kf[2*ntp+1][0] = r[2]; kf[2*ntp+1][1] = r[3];
                }
#pragma unroll
                for (int nt = 0; nt < 8; nt++) mma16816(S[nt], qf[ks], kf[nt]);
            }

            const bool full = (ktb >= qb + 127 - WIN) && (ktb + 64 <= qb);
            if (!full) {
#pragma unroll
                for (int nt = 0; nt < 8; nt++) {
                    int j = ktb + nt * 8 + jc;
                    if (j > i0 || j < i0 - WIN)         S[nt][0] = -1e30f;
                    if (j + 1 > i0 || j + 1 < i0 - WIN) S[nt][1] = -1e30f;
                    if (j > i1 || j < i1 - WIN)         S[nt][2] = -1e30f;
                    if (j + 1 > i1 || j + 1 < i1 - WIN) S[nt][3] = -1e30f;
                }
            }

            float mx0 = -1e30f, mx1 = -1e30f;
#pragma unroll
            for (int nt = 0; nt < 8; nt++) {
                mx0 = fmaxf(mx0, fmaxf(S[nt][0], S[nt][1]));
                mx1 = fmaxf(mx1, fmaxf(S[nt][2], S[nt][3]));
            }
            mx0 = fmaxf(mx0, __shfl_xor_sync(0xffffffffu, mx0, 1));
            mx0 = fmaxf(mx0, __shfl_xor_sync(0xffffffffu, mx0, 2));
            mx1 = fmaxf(mx1, __shfl_xor_sync(0xffffffffu, mx1, 1));
            mx1 = fmaxf(mx1, __shfl_xor_sync(0xffffffffu, mx1, 2));
            const float mn0 = fmaxf(m0, mx0);
            const float mn1 = fmaxf(m1, mx1);
            const bool stable = __all_sync(0xffffffffu, (mn0 == m0) & (mn1 == m1));
            if (!stable) {
                const float sc0 = exp2f((m0 - mn0) * 1.44269504f);
                const float sc1 = exp2f((m1 - mn1) * 1.44269504f);
                m0 = mn0; m1 = mn1;
                l0 *= sc0; l1 *= sc1;
#pragma unroll
                for (int nt = 0; nt < 8; nt++) {
                    O[nt][0] *= sc0; O[nt][1] *= sc0;
                    O[nt][2] *= sc1; O[nt][3] *= sc1;
                }
            }
            float rs0 = 0.f, rs1 = 0.f;
#pragma unroll
            for (int nt = 0; nt < 8; nt++) {
                S[nt][0] = exp2f((S[nt][0] - m0) * 1.44269504f);
                S[nt][1] = exp2f((S[nt][1] - m0) * 1.44269504f);
                S[nt][2] = exp2f((S[nt][2] - m1) * 1.44269504f);
                S[nt][3] = exp2f((S[nt][3] - m1) * 1.44269504f);
                rs0 += S[nt][0] + S[nt][1];
                rs1 += S[nt][2] + S[nt][3];
            }
            rs0 += __shfl_xor_sync(0xffffffffu, rs0, 1);
            rs0 += __shfl_xor_sync(0xffffffffu, rs0, 2);
            rs1 += __shfl_xor_sync(0xffffffffu, rs1, 1);
            rs1 += __shfl_xor_sync(0xffffffffu, rs1, 2);
            l0 += rs0; l1 += rs1;

            uint32_t pa[4][4];
#pragma unroll
            for (int ks = 0; ks < 4; ks++) {
                pa[ks][0] = pack_f16(S[2*ks][0],   S[2*ks][1]);
                pa[ks][1] = pack_f16(S[2*ks][2],   S[2*ks][3]);
                pa[ks][2] = pack_f16(S[2*ks+1][0], S[2*ks+1][1]);
                pa[ks][3] = pack_f16(S[2*ks+1][2], S[2*ks+1][3]);
            }

#pragma unroll
            for (int ks = 0; ks < 4; ks++) {
                const uint32_t vbase = bV + vrow + (uint32_t)(ks * 2048);
                uint32_t vf[8][2];
#pragma unroll
                for (int ntp = 0; ntp < 4; ntp++) {
                    uint32_t r[4];
                    ldsm_x4t(r, vbase + (uint32_t)((ntp * 32 + v_cb) ^ vxor));
                    vf[2*ntp][0] = r[0]; vf[2*ntp][1] = r[1];
                    vf[2*ntp+1][0] = r[2]; vf[2*ntp+1][1] = r[3];
                }
#pragma unroll
                for (int nt = 0; nt < 8; nt++) mma16816(O[nt], pa[ks], vf[nt]);
            }
        }
    }

    const float inv0 = 1.f / l0;
    const float inv1 = 1.f / l1;
    const int row0 = qb + warp * 16 + (lane >> 2);
    const int colb = h * HD + jc;
#pragma unroll
    for (int nt = 0; nt < 8; nt++) {
        size_t o = (size_t)row0 * DM + colb + nt * 8;
        *(uint32_t*)(O_out + o) = pack_f16(O[nt][0] * inv0, O[nt][1] * inv0);
        o += (size_t)8 * DM;
        *(uint32_t*)(O_out + o) = pack_f16(O[nt][2] * inv1, O[nt][3] * inv1);
    }

    // ---- fused wo transpose tail: 4 tiles per CTA (2048 total) ----
    __syncthreads();
    float (*t)[33] = (float(*)[33])sm;   // 8448 B, fits in ATTN_SMEM
    const int f = (h * 16 + qt) * 4;
#pragma unroll
    for (int i = 0; i < 4; i++) {
        t_tile1(wo, two, DM, DM, f + i, t);
        __syncthreads();
    }
}

// ---------------- launch --------------------------------------------------------
extern "C" void kernel_launch(void* const* d_in, const int* in_sizes, int n_in,
                              void* d_out, int out_size)
{
    const float* x  = (const float*)d_in[0];
    const float* wq = (const float*)d_in[1];
    const float* wk = (const float*)d_in[2];
    const float* wv = (const float*)d_in[3];
    const float* wo = (const float*)d_in[4];
    const float* fc = (const float*)d_in[5];
    const float* fs = (const float*)d_in[6];
    float* out = (float*)d_out;

    __half *xp, *twq, *twk, *twv, *two, *q, *k, *v, *ao;
    cudaGetSymbolAddress((void**)&xp,  g_x);
    cudaGetSymbolAddress((void**)&twq, g_wq);  cudaGetSymbolAddress((void**)&twk, g_wk);
    cudaGetSymbolAddress((void**)&twv, g_wv);  cudaGetSymbolAddress((void**)&two, g_wo);
    cudaGetSymbolAddress((void**)&q,   g_Q);   cudaGetSymbolAddress((void**)&k,   g_K);
    cudaGetSymbolAddress((void**)&v,   g_V);   cudaGetSymbolAddress((void**)&ao,  g_AO);

    cudaFuncSetAttribute(qkv_gemm, cudaFuncAttributeMaxDynamicSharedMemorySize, GEMM_SMEM);
    cudaFuncSetAttribute(out_gemm, cudaFuncAttributeMaxDynamicSharedMemorySize, GEMM_SMEM);
    cudaFuncSetAttribute(attn_mma, cudaFuncAttributeMaxDynamicSharedMemorySize, ATTN_SMEM);

    prepass_all<<<5120, 256>>>(x, wq, wk, wv, xp, twq, twk, twv);

    qkv_gemm<<<dim3(24, 16), 256, GEMM_SMEM>>>(xp, twq, twk, twv, q, k, v, fc, fs);

    attn_mma<<<dim3(SQ / 128, NH), 256, ATTN_SMEM>>>(q, k, v, ao, wo, two);

    out_gemm<<<dim3(16, 16), 256, GEMM_SMEM>>>(ao, two, out);
}

// round 13
// speedup vs baseline: 2.5702x; 1.0214x over previous
#include <cuda_runtime.h>
#include <cuda_fp16.h>
#include <math.h>
#include <stdint.h>

#define SQ 2048
#define DM 2048
#define NH 32
#define NKV 8
#define HD 64
#define WIN 1024
#define KVD (NKV*HD)

// ---------------- scratch (device globals) -----------------------------------
__device__ __half g_x  [SQ*DM];
__device__ __half g_wq [DM*DM];                 // [N][K]
__device__ __half g_wk [KVD*DM];
__device__ __half g_wv [KVD*DM];
__device__ __half g_wo [DM*DM];
__device__ __half g_Q  [SQ*DM];
__device__ __half g_K  [SQ*KVD];
__device__ __half g_V  [SQ*KVD];
__device__ __half g_AO [SQ*DM];

// ---------------- helpers -----------------------------------------------------
__device__ __forceinline__ uint32_t smem_u32(const void* p) {
    uint32_t a;
    asm("{ .reg .u64 t; cvta.to.shared.u64 t, %1; cvt.u32.u64 %0, t; }" : "=r"(a) : "l"(p));
    return a;
}
__device__ __forceinline__ void cp16(uint32_t s, const void* g) {
    asm volatile("cp.async.cg.shared.global [%0], [%1], 16;" :: "r"(s), "l"(g));
}
__device__ __forceinline__ void cp_commit() { asm volatile("cp.async.commit_group;" ::: "memory"); }
template<int N> __device__ __forceinline__ void cp_wait() {
    asm volatile("cp.async.wait_group %0;" :: "n"(N) : "memory");
}
__device__ __forceinline__ void ldsm_x4(uint32_t* r, uint32_t addr) {
    asm volatile("ldmatrix.sync.aligned.m8n8.x4.shared.b16 {%0,%1,%2,%3}, [%4];"
                 : "=r"(r[0]), "=r"(r[1]), "=r"(r[2]), "=r"(r[3]) : "r"(addr));
}
__device__ __forceinline__ void ldsm_x4t(uint32_t* r, uint32_t addr) {
    asm volatile("ldmatrix.sync.aligned.m8n8.x4.trans.shared.b16 {%0,%1,%2,%3}, [%4];"
                 : "=r"(r[0]), "=r"(r[1]), "=r"(r[2]), "=r"(r[3]) : "r"(addr));
}
__device__ __forceinline__ void mma16816(float* c, const uint32_t* a, const uint32_t* b) {
    asm volatile("mma.sync.aligned.m16n8k16.row.col.f32.f16.f16.f32 "
                 "{%0,%1,%2,%3}, {%4,%5,%6,%7}, {%8,%9}, {%0,%1,%2,%3};"
                 : "+f"(c[0]), "+f"(c[1]), "+f"(c[2]), "+f"(c[3])
                 : "r"(a[0]), "r"(a[1]), "r"(a[2]), "r"(a[3]), "r"(b[0]), "r"(b[1]));
}
__device__ __forceinline__ uint32_t pack_f16(float lo, float hi) {
    uint32_t r;
    asm("cvt.rn.f16x2.f32 %0, %1, %2;" : "=r"(r) : "f"(hi), "f"(lo));
    return r;
}
// fast exp2 (single MUFU.EX2)
__device__ __forceinline__ float ex2(float x) {
    float r;
    asm("ex2.approx.ftz.f32 %0, %1;" : "=f"(r) : "f"(x));
    return r;
}
#define LOG2E 1.44269504f

// ---------------- weight transpose tile ----------------------------------------
__device__ __forceinline__ void t_tile1(const float* __restrict__ W, __half* __restrict__ T,
                                        int K, int N, int tile, float (*t)[33])
{
    const int tid = threadIdx.x;
    const int ntn = N >> 5;
    const int k0 = (tile / ntn) << 6;
    const int n0 = (tile % ntn) << 5;
#pragma unroll
    for (int it = 0; it < 8; it++) {
        int idx = tid + it * 256;
        int r = idx >> 5, c = idx & 31;
        t[r][c] = W[(size_t)(k0 + r) * N + n0 + c];
    }
    __syncthreads();
    const int n  = tid >> 3;
    const int kk = tid & 7;
#pragma unroll
    for (int it = 0; it < 4; it++) {
        int kp = kk + it * 8;
        *(uint32_t*)(T + (size_t)(n0 + n) * K + k0 + 2 * kp) =
            pack_f16(t[2*kp][n], t[2*kp+1][n]);
    }
}

// ---------------- pre-pass: x convert + wq/wk/wv transposes --------------------
__global__ __launch_bounds__(256)
void prepass_all(const float* __restrict__ x,
                 const float* __restrict__ wq, const float* __restrict__ wk,
                 const float* __restrict__ wv,
                 __half* xo, __half* twq, __half* twk, __half* twv)
{
    __shared__ float t[64][33];
    int b = blockIdx.x;
    if (b < 2048) {
#pragma unroll
        for (int it = 0; it < 2; it++) {
            int i = b * 512 + it * 256 + threadIdx.x;
            float4 v = ((const float4*)x)[i];
            ((uint2*)xo)[i] = make_uint2(pack_f16(v.x, v.y), pack_f16(v.z, v.w));
        }
        return;
    }
    b -= 2048;
    if (b < 2048)        t_tile1(wq, twq, DM, DM,  b,        t);
    else if (b < 2560)   t_tile1(wk, twk, DM, KVD, b - 2048, t);
    else                 t_tile1(wv, twv, DM, KVD, b - 2560, t);
}

// ---------------- GEMM mainloop: fp16 single-term, 3-stage ---------------------
static constexpr int GEMM_STAGE = 32768;
static constexpr int GEMM_SMEM  = 3 * GEMM_STAGE;

struct GemmAcc { float a[4][4][4]; };

__device__ __forceinline__ void gemm_mainloop(
    const __half* __restrict__ A, const __half* __restrict__ B,
    int brow, int bcol, int K, uint32_t sbase, GemmAcc& acc)
{
    const int tid  = threadIdx.x;
    const int warp = tid >> 5;
    const int lane = tid & 31;
    const int wm   = (warp & 1) * 64;
    const int wn   = (warp >> 1) * 32;

    const int xo    = (lane & 7) << 4;
    const int a_row = wm + (lane & 7) + 8 * ((lane >> 3) & 1);
    const int a_kb  = 16 * (lane >> 4);
    const int b_row = wn + (lane >> 4) * 8 + (lane & 7);
    const int b_kb  = 16 * ((lane >> 3) & 1);

    const int ld_r0 = tid >> 3;
    const uint32_t ld_col = (uint32_t)(((tid & 7) * 16) ^ (((tid >> 3) & 7) << 4));
    const int ld_ke = (tid & 7) * 8;

    auto load_stage = [&](int s, int k0) {
        uint32_t base = sbase + s * GEMM_STAGE;
#pragma unroll
        for (int it = 0; it < 4; it++) {
            int r = ld_r0 + it * 32;
            uint32_t off = (uint32_t)(r * 128) + ld_col;
            cp16(base + off,         A + (size_t)(brow + r) * K + k0 + ld_ke);
            cp16(base + 16384 + off, B + (size_t)(bcol + r) * K + k0 + ld_ke);
        }
    };

    const int nch = K >> 6;
    load_stage(0, 0);  cp_commit();
    load_stage(1, 64); cp_commit();

    int s = 0;
    for (int c = 0; c < nch; c++) {
        cp_wait<1>();
        __syncthreads();
        if (c + 2 < nch) load_stage((s + 2 >= 3) ? s - 1 : s + 2, (c + 2) << 6);
        cp_commit();

        uint32_t base = sbase + s * GEMM_STAGE;
#pragma unroll
        for (int ks = 0; ks < 4; ks++) {
            const int kb = ks * 32;
            const uint32_t acol  = (uint32_t)((kb + a_kb) ^ xo);
            const uint32_t bcol2 = (uint32_t)((kb + b_kb) ^ xo);
            uint32_t bh[4][2];
#pragma unroll
            for (int ntp = 0; ntp < 2; ntp++) {
                uint32_t r[4];
                ldsm_x4(r, base + 16384 + (uint32_t)((b_row + ntp * 16) * 128) + bcol2);
                bh[2*ntp][0] = r[0]; bh[2*ntp][1] = r[1];
                bh[2*ntp+1][0] = r[2]; bh[2*ntp+1][1] = r[3];
            }
#pragma unroll
            for (int mt = 0; mt < 4; mt++) {
                uint32_t ah[4];
                ldsm_x4(ah, base + (uint32_t)((a_row + mt * 16) * 128) + acol);
#pragma unroll
                for (int nt = 0; nt < 4; nt++) mma16816(acc.a[mt][nt], ah, bh[nt]);
            }
        }
        s = (s + 1 >= 3) ? 0 : s + 1;
    }
}

// Fused QKV projection
__global__ __launch_bounds__(256, 2)
void qkv_gemm(const __half* __restrict__ x,
              const __half* __restrict__ wq, const __half* __restrict__ wk,
              const __half* __restrict__ wv,
              __half* __restrict__ q, __half* __restrict__ k, __half* __restrict__ v,
              const float* __restrict__ fc, const float* __restrict__ fs)
{
    extern __shared__ char sm[];
    const uint32_t sbase = smem_u32(sm);
    const int bx   = blockIdx.x;
    const int brow = blockIdx.y * 128;

    const __half* B;
    __half* C;
    int N, bcol, mode;
    if (bx < 16)      { B = wq; C = q; N = DM;  bcol = bx * 128;        mode = 1; }
    else if (bx < 20) { B = wk; C = k; N = KVD; bcol = (bx - 16) * 128; mode = 2; }
    else              { B = wv; C = v; N = KVD; bcol = (bx - 20) * 128; mode = 3; }

    GemmAcc acc;
#pragma unroll
    for (int i = 0; i < 4; i++)
#pragma unroll
        for (int j = 0; j < 4; j++)
#pragma unroll
            for (int e = 0; e < 4; e++) acc.a[i][j][e] = 0.f;

    gemm_mainloop(x, B, brow, bcol, DM, sbase, acc);

    const int warp = threadIdx.x >> 5;
    const int lane = threadIdx.x & 31;
    const int mrow0 = brow + (warp & 1) * 64 + (lane >> 2);
    const int ncol0 = bcol + (warp >> 1) * 32 + 2 * (lane & 3);
#pragma unroll
    for (int mt = 0; mt < 4; mt++) {
#pragma unroll
        for (int half = 0; half < 2; half++) {
            const int m = mrow0 + mt * 16 + half * 8;
#pragma unroll
            for (int nt = 0; nt < 4; nt++) {
                float v0 = acc.a[mt][nt][half * 2];
                float v1 = acc.a[mt][nt][half * 2 + 1];
                const int n = ncol0 + nt * 8;
                if (mode != 3) {
                    int p = (n & (HD - 1)) >> 1;
                    float cs = fc[m * (HD / 2) + p];
                    float sn = fs[m * (HD / 2) + p];
                    float a = v0, b = v1;
                    v0 = a * cs - b * sn;
                    v1 = a * sn + b * cs;
                    if (mode == 1) { v0 *= 0.125f; v1 *= 0.125f; }
                }
                *(uint32_t*)(C + (size_t)m * N + n) = pack_f16(v0, v1);
            }
        }
    }
}

// Output projection
__global__ __launch_bounds__(256, 2)
void out_gemm(const __half* __restrict__ A, const __half* __restrict__ B,
              float* __restrict__ C)
{
    extern __shared__ char sm[];
    const uint32_t sbase = smem_u32(sm);
    const int brow = blockIdx.y * 128;
    const int bcol = blockIdx.x * 128;

    GemmAcc acc;
#pragma unroll
    for (int i = 0; i < 4; i++)
#pragma unroll
        for (int j = 0; j < 4; j++)
#pragma unroll
            for (int e = 0; e < 4; e++) acc.a[i][j][e] = 0.f;

    gemm_mainloop(A, B, brow, bcol, DM, sbase, acc);

    const int warp = threadIdx.x >> 5;
    const int lane = threadIdx.x & 31;
    const int mrow0 = brow + (warp & 1) * 64 + (lane >> 2);
    const int ncol0 = bcol + (warp >> 1) * 32 + 2 * (lane & 3);
#pragma unroll
    for (int mt = 0; mt < 4; mt++) {
#pragma unroll
        for (int half = 0; half < 2; half++) {
            const int m = mrow0 + mt * 16 + half * 8;
#pragma unroll
            for (int nt = 0; nt < 4; nt++) {
                const int n = ncol0 + nt * 8;
                *(float2*)(C + (size_t)m * DM + n) =
                    make_float2(acc.a[mt][nt][half * 2], acc.a[mt][nt][half * 2 + 1]);
            }
        }
    }
}

// ---------------- MMA flash attention + fused wo transpose tail ----------------
static constexpr int ATTN_STAGE = 16384;
static constexpr int ATTN_SMEM  = 16384 + 2 * ATTN_STAGE;

__global__ __launch_bounds__(256, 2)
void attn_mma(const __half* __restrict__ Qg, const __half* __restrict__ Kg,
              const __half* __restrict__ Vg, __half* __restrict__ O_out,
              const float* __restrict__ wo, __half* __restrict__ two)
{
    extern __shared__ char sm[];
    const uint32_t sb = smem_u32(sm);
    const int tid  = threadIdx.x;
    const int warp = tid >> 5;
    const int lane = tid & 31;
    const int qt   = (int)(gridDim.x - 1 - blockIdx.x);   // long CTAs launch first
    const int h    = blockIdx.y;
    const int kvh  = h >> 2;
    const int qb   = qt * 128;

    const uint32_t sQ  = sb;
    const uint32_t st0 = sb + 16384;

    const int kt0   = max(0, (qb - WIN) >> 6);
    const int ktmax = 2 * qt + 1;

    const int ld_r0 = tid >> 3;
    const uint32_t ld_col = (uint32_t)(((tid & 7) * 16) ^ (((tid >> 3) & 7) << 4));
    const int ld_ke = (tid & 7) * 8;

#pragma unroll
    for (int it = 0; it < 4; it++) {
        int r = ld_r0 + it * 32;
        cp16(sQ + (uint32_t)(r * 128) + ld_col, Qg + (size_t)(qb + r) * DM + h * HD + ld_ke);
    }
    auto load_kv = [&](uint32_t base, int kt) {
#pragma unroll
        for (int it = 0; it < 2; it++) {
            int r = ld_r0 + it * 32;
            uint32_t off = (uint32_t)(r * 128) + ld_col;
            size_t go = (size_t)(kt * 64 + r) * KVD + kvh * HD + ld_ke;
            cp16(base + off,        Kg + go);
            cp16(base + 8192 + off, Vg + go);
        }
    };
    load_kv(st0, kt0);
    cp_commit();
    cp_wait<0>();
    __syncthreads();

    const int qxor  = (lane & 7) << 4;
    const int q_row = warp * 16 + (lane & 7) + 8 * ((lane >> 3) & 1);
    const int q_kb  = 16 * (lane >> 4);
    uint32_t qf[4][4];
#pragma unroll
    for (int ks = 0; ks < 4; ks++)
        ldsm_x4(qf[ks], sQ + (uint32_t)(q_row * 128) + (uint32_t)((ks * 32 + q_kb) ^ qxor));

    float O[8][4];
#pragma unroll
    for (int nt = 0; nt < 8; nt++)
#pragma unroll
        for (int e = 0; e < 4; e++) O[nt][e] = 0.f;
    float m0 = -1e20f, m1 = -1e20f, l0 = 0.f, l1 = 0.f;

    const int i0 = qb + warp * 16 + (lane >> 2);
    const int i1 = i0 + 8;
    const int jc = 2 * (lane & 3);
    const int wrow0 = qb + warp * 16;
    const uint32_t krow = (uint32_t)(((lane >> 4) * 8 + (lane & 7)) * 128);
    const int kxor = (lane & 7) << 4;
    const int k_kb = 16 * ((lane >> 3) & 1);
    const uint32_t vrow = (uint32_t)((lane & 15) * 128);
    const int vxor = (lane & 7) << 4;
    const int v_cb = (lane >> 4) * 16;

    for (int kt = kt0; kt <= ktmax; kt++) {
        const int buf = (kt - kt0) & 1;
        cp_wait<0>();
        __syncthreads();
        if (kt < ktmax) load_kv(st0 + (buf ^ 1) * ATTN_STAGE, kt + 1);
        cp_commit();

        const int ktb = kt * 64;
        const bool act = (ktb <= wrow0 + 15) && (ktb + 63 >= wrow0 - WIN);
        if (act) {
            const uint32_t bK = st0 + buf * ATTN_STAGE;
            const uint32_t bV = bK + 8192;

            float S[8][4];
#pragma unroll
            for (int nt = 0; nt < 8; nt++)
#pragma unroll
                for (int e = 0; e < 4; e++) S[nt][e] = 0.f;

#pragma unroll
            for (int ks = 0; ks < 4; ks++) {
                const uint32_t kcol = (uint32_t)((ks * 32 + k_kb) ^ kxor);
                uint32_t kf[8][2];
#pragma unroll
                for (int ntp = 0; ntp < 4; ntp++) {
                    uint32_t r[4];
                    ldsm_x4(r, bK + krow + (uint32_t)(ntp * 2048) + kcol);
                    kf[2*ntp][0] = r[0]; kf[2*ntp][1] = r[1];
                    kf[2*ntp+1][0] = r[2]; kf[2*ntp+1][1] = r[3];
                }
#pragma unroll
                for (int nt = 0; nt < 8; nt++) mma16816(S[nt], qf[ks], kf[nt]);
            }

            const bool full = (ktb >= qb + 127 - WIN) && (ktb + 64 <= qb);
            if (!full) {
#pragma unroll
                for (int nt = 0; nt < 8; nt++) {
                    int j = ktb + nt * 8 + jc;
                    if (j > i0 || j < i0 - WIN)         S[nt][0] = -1e30f;
                    if (j + 1 > i0 || j + 1 < i0 - WIN) S[nt][1] = -1e30f;
                    if (j > i1 || j < i1 - WIN)         S[nt][2] = -1e30f;
                    if (j + 1 > i1 || j + 1 < i1 - WIN) S[nt][3] = -1e30f;
                }
            }

            float mx0 = -1e30f, mx1 = -1e30f;
#pragma unroll
            for (int nt = 0; nt < 8; nt++) {
                mx0 = fmaxf(mx0, fmaxf(S[nt][0], S[nt][1]));
                mx1 = fmaxf(mx1, fmaxf(S[nt][2], S[nt][3]));
            }
            mx0 = fmaxf(mx0, __shfl_xor_sync(0xffffffffu, mx0, 1));
            mx0 = fmaxf(mx0, __shfl_xor_sync(0xffffffffu, mx0, 2));
            mx1 = fmaxf(mx1, __shfl_xor_sync(0xffffffffu, mx1, 1));
            mx1 = fmaxf(mx1, __shfl_xor_sync(0xffffffffu, mx1, 2));
            const float mn0 = fmaxf(m0, mx0);
            const float mn1 = fmaxf(m1, mx1);
            const bool stable = __all_sync(0xffffffffu, (mn0 == m0) & (mn1 == m1));
            if (!stable) {
                const float sc0 = ex2((m0 - mn0) * LOG2E);
                const float sc1 = ex2((m1 - mn1) * LOG2E);
                m0 = mn0; m1 = mn1;
                l0 *= sc0; l1 *= sc1;
#pragma unroll
                for (int nt = 0; nt < 8; nt++) {
                    O[nt][0] *= sc0; O[nt][1] *= sc0;
                    O[nt][2] *= sc1; O[nt][3] *= sc1;
                }
            }
            const float mlg0 = m0 * LOG2E;
            const float mlg1 = m1 * LOG2E;
            float rs0 = 0.f, rs1 = 0.f;
#pragma unroll
            for (int nt = 0; nt < 8; nt++) {
                S[nt][0] = ex2(fmaf(S[nt][0], LOG2E, -mlg0));
                S[nt][1] = ex2(fmaf(S[nt][1], LOG2E, -mlg0));
                S[nt][2] = ex2(fmaf(S[nt][2], LOG2E, -mlg1));
                S[nt][3] = ex2(fmaf(S[nt][3], LOG2E, -mlg1));
                rs0 += S[nt][0] + S[nt][1];
                rs1 += S[nt][2] + S[nt][3];
            }
            rs0 += __shfl_xor_sync(0xffffffffu, rs0, 1);
            rs0 += __shfl_xor_sync(0xffffffffu, rs0, 2);
            rs1 += __shfl_xor_sync(0xffffffffu, rs1, 1);
            rs1 += __shfl_xor_sync(0xffffffffu, rs1, 2);
            l0 += rs0; l1 += rs1;

            uint32_t pa[4][4];
#pragma unroll
            for (int ks = 0; ks < 4; ks++) {
                pa[ks][0] = pack_f16(S[2*ks][0],   S[2*ks][1]);
                pa[ks][1] = pack_f16(S[2*ks][2],   S[2*ks][3]);
                pa[ks][2] = pack_f16(S[2*ks+1][0], S[2*ks+1][1]);
                pa[ks][3] = pack_f16(S[2*ks+1][2], S[2*ks+1][3]);
            }

#pragma unroll
            for (int ks = 0; ks < 4; ks++) {
                const uint32_t vbase = bV + vrow + (uint32_t)(ks * 2048);
                uint32_t vf[8][2];
#pragma unroll
                for (int ntp = 0; ntp < 4; ntp++) {
                    uint32_t r[4];
                    ldsm_x4t(r, vbase + (uint32_t)((ntp * 32 + v_cb) ^ vxor));
                    vf[2*ntp][0] = r[0]; vf[2*ntp][1] = r[1];
                    vf[2*ntp+1][0] = r[2]; vf[2*ntp+1][1] = r[3];
                }
#pragma unroll
                for (int nt = 0; nt < 8; nt++) mma16816(O[nt], pa[ks], vf[nt]);
            }
        }
    }

    const float inv0 = 1.f / l0;
    const float inv1 = 1.f / l1;
    const int row0 = qb + warp * 16 + (lane >> 2);
    const int colb = h * HD + jc;
#pragma unroll
    for (int nt = 0; nt < 8; nt++) {
        size_t o = (size_t)row0 * DM + colb + nt * 8;
        *(uint32_t*)(O_out + o) = pack_f16(O[nt][0] * inv0, O[nt][1] * inv0);
        o += (size_t)8 * DM;
        *(uint32_t*)(O_out + o) = pack_f16(O[nt][2] * inv1, O[nt][3] * inv1);
    }

    // ---- fused wo transpose tail: 4 tiles per CTA (2048 total) ----
    __syncthreads();
    float (*t)[33] = (float(*)[33])sm;
    const int f = (h * 16 + qt) * 4;
#pragma unroll
    for (int i = 0; i < 4; i++) {
        t_tile1(wo, two, DM, DM, f + i, t);
        __syncthreads();
    }
}

// ---------------- launch --------------------------------------------------------
extern "C" void kernel_launch(void* const* d_in, const int* in_sizes, int n_in,
                              void* d_out, int out_size)
{
    const float* x  = (const float*)d_in[0];
    const float* wq = (const float*)d_in[1];
    const float* wk = (const float*)d_in[2];
    const float* wv = (const float*)d_in[3];
    const float* wo = (const float*)d_in[4];
    const float* fc = (const float*)d_in[5];
    const float* fs = (const float*)d_in[6];
    float* out = (float*)d_out;

    __half *xp, *twq, *twk, *twv, *two, *q, *k, *v, *ao;
    cudaGetSymbolAddress((void**)&xp,  g_x);
    cudaGetSymbolAddress((void**)&twq, g_wq);  cudaGetSymbolAddress((void**)&twk, g_wk);
    cudaGetSymbolAddress((void**)&twv, g_wv);  cudaGetSymbolAddress((void**)&two, g_wo);
    cudaGetSymbolAddress((void**)&q,   g_Q);   cudaGetSymbolAddress((void**)&k,   g_K);
    cudaGetSymbolAddress((void**)&v,   g_V);   cudaGetSymbolAddress((void**)&ao,  g_AO);

    cudaFuncSetAttribute(qkv_gemm, cudaFuncAttributeMaxDynamicSharedMemorySize, GEMM_SMEM);
    cudaFuncSetAttribute(out_gemm, cudaFuncAttributeMaxDynamicSharedMemorySize, GEMM_SMEM);
    cudaFuncSetAttribute(attn_mma, cudaFuncAttributeMaxDynamicSharedMemorySize, ATTN_SMEM);

    prepass_all<<<5120, 256>>>(x, wq, wk, wv, xp, twq, twk, twv);

    qkv_gemm<<<dim3(24, 16), 256, GEMM_SMEM>>>(xp, twq, twk, twv, q, k, v, fc, fs);

    attn_mma<<<dim3(SQ / 128, NH), 256, ATTN_SMEM>>>(q, k, v, ao, wo, two);

    out_gemm<<<dim3(16, 16), 256, GEMM_SMEM>>>(ao, two, out);
}